// round 1
// baseline (speedup 1.0000x reference)
#include <cuda_runtime.h>
#include <math.h>

#define BATCH 2
#define C 512
#define L 4096
#define NH 4
#define HD 128
#define GROUPS 32
#define CPG (C / GROUPS)   // 16
#define EPS 1e-5f

// ---------------- scratch (static device globals; no allocation) ----------------
__device__ float g_xn[(size_t)BATCH * C * L];        // 16 MB
__device__ float g_qkv[(size_t)BATCH * 3 * C * L];   // 48 MB
__device__ float g_att[(size_t)BATCH * C * L];       // 16 MB

// ---------------- GroupNorm ----------------
// grid (GROUPS, BATCH), 256 threads. Each block normalizes 16 channels x 4096.
__global__ void __launch_bounds__(256) groupnorm_kernel(const float* __restrict__ x,
                                                        const float* __restrict__ gw,
                                                        const float* __restrict__ gb) {
    const int g = blockIdx.x, b = blockIdx.y;
    const int tid = threadIdx.x;
    const size_t base = ((size_t)b * C + g * CPG) * L;
    const int SPAN = CPG * L;  // 65536
    const float4* x4 = (const float4*)(x + base);
    float s = 0.f, ss = 0.f;
    for (int i = tid; i < SPAN / 4; i += 256) {
        float4 v = x4[i];
        s  += v.x + v.y + v.z + v.w;
        ss += v.x * v.x + v.y * v.y + v.z * v.z + v.w * v.w;
    }
    __shared__ float rs[256], rss[256];
    rs[tid] = s; rss[tid] = ss;
    __syncthreads();
    for (int off = 128; off; off >>= 1) {
        if (tid < off) { rs[tid] += rs[tid + off]; rss[tid] += rss[tid + off]; }
        __syncthreads();
    }
    __shared__ float s_mean, s_rstd;
    if (tid == 0) {
        float mean = rs[0] / SPAN;
        float var  = rss[0] / SPAN - mean * mean;
        s_mean = mean;
        s_rstd = rsqrtf(var + EPS);
    }
    __syncthreads();
    const float mean = s_mean, rstd = s_rstd;
    float4* o4 = (float4*)(g_xn + base);
    for (int i = tid; i < SPAN / 4; i += 256) {
        int c = g * CPG + (i >> 10);  // 1024 float4 per channel
        float ga = gw[c] * rstd;
        float be = gb[c] - mean * ga;
        float4 v = x4[i];
        float4 o;
        o.x = v.x * ga + be; o.y = v.y * ga + be;
        o.z = v.z * ga + be; o.w = v.w * ga + be;
        o4[i] = o;
    }
}

// ---------------- generic GEMM: C[b][m][n] = sum_k A[m][k]*B[b][k][n] (+bias[m]) (+resid[b][m][n]) ----------------
#define BM 64
#define BN 64
#define BKK 16

__global__ void __launch_bounds__(256) gemm_kernel(const float* __restrict__ A,
                                                   const float* __restrict__ Bmat,
                                                   const float* __restrict__ bias,
                                                   const float* __restrict__ resid,
                                                   float* __restrict__ Cout,
                                                   int M, int N, int K) {
    const int bz = blockIdx.z;
    Bmat += (size_t)bz * K * N;
    Cout += (size_t)bz * M * N;
    if (resid) resid += (size_t)bz * M * N;
    const int m0 = blockIdx.y * BM, n0 = blockIdx.x * BN;
    const int tid = threadIdx.x;
    const int tx = tid & 15, ty = tid >> 4;

    __shared__ float As[BKK][BM + 4];  // +4 pad: 2-way max conflict on stores, keeps 16B alignment
    __shared__ float Bs[BKK][BN];

    float acc[4][4] = {};
    const int a_k = tid & 15, a_m = tid >> 4;  // 4 m-rows, stride 16
    const int b_n = tid & 63, b_k = tid >> 6;  // 4 k-rows, stride 4

    for (int k0 = 0; k0 < K; k0 += BKK) {
        #pragma unroll
        for (int r = 0; r < 4; r++)
            As[a_k][a_m + r * 16] = A[(size_t)(m0 + a_m + r * 16) * K + k0 + a_k];
        #pragma unroll
        for (int r = 0; r < 4; r++)
            Bs[b_k + r * 4][b_n] = Bmat[(size_t)(k0 + b_k + r * 4) * N + n0 + b_n];
        __syncthreads();
        #pragma unroll
        for (int k = 0; k < BKK; k++) {
            float4 a  = *(const float4*)&As[k][ty * 4];
            float4 bv = *(const float4*)&Bs[k][tx * 4];
            float av[4] = {a.x, a.y, a.z, a.w};
            float bb[4] = {bv.x, bv.y, bv.z, bv.w};
            #pragma unroll
            for (int i = 0; i < 4; i++)
                #pragma unroll
                for (int j = 0; j < 4; j++) acc[i][j] += av[i] * bb[j];
        }
        __syncthreads();
    }
    #pragma unroll
    for (int i = 0; i < 4; i++) {
        int m = m0 + ty * 4 + i;
        float bia = bias ? bias[m] : 0.f;
        float4 o;
        o.x = acc[i][0] + bia; o.y = acc[i][1] + bia;
        o.z = acc[i][2] + bia; o.w = acc[i][3] + bia;
        size_t off = (size_t)m * N + n0 + tx * 4;
        if (resid) {
            float4 r = *(const float4*)&resid[off];
            o.x += r.x; o.y += r.y; o.z += r.z; o.w += r.w;
        }
        *(float4*)&Cout[off] = o;
    }
}

// ---------------- flash attention ----------------
// q,k,v layouts: [b][3C][L] inside g_qkv; per (b,head) each is [HD=128][L].
// Block: 64 queries; loop over 64-key tiles; online softmax.
#define BQ 64
#define BKT 64
#define SQS 68  // smem row stride (pad 4: float4-aligned, kills c-stride bank conflicts)

__global__ void __launch_bounds__(256) attn_kernel() {
    extern __shared__ float sm[];
    float* q_s     = sm;                     // [HD][SQS], pre-scaled q
    float* kv_s    = q_s + HD * SQS;         // [HD][SQS], K then V
    float* p_s     = kv_s + HD * SQS;        // [BKT][SQS] stored transposed: p_s[e][d]
    float* alpha_s = p_s + BKT * SQS;        // [BQ]

    const int tid = threadIdx.x;
    const int qb = blockIdx.x, bh = blockIdx.y;
    const int b = bh >> 2, h = bh & 3;
    const float* qp = g_qkv + ((size_t)b * 3 * C + h * HD) * L;
    const float* kp = qp + (size_t)C * L;
    const float* vp = qp + (size_t)2 * C * L;
    const int q0 = qb * BQ;
    const float scale = 0.08838834764831845f;  // 1/sqrt(128)

    for (int i = tid; i < HD * BQ; i += 256) {
        int c = i >> 6, d = i & 63;
        q_s[c * SQS + d] = qp[(size_t)c * L + q0 + d] * scale;
    }
    const int tx = tid & 15, ty = tid >> 4;
    const int oc0 = ty * 8;   // out accumulator: 8 channels
    const int od0 = tx * 4;   // out accumulator: 4 queries
    float m_i[4], l_i[4];
    #pragma unroll
    for (int i = 0; i < 4; i++) { m_i[i] = -1e30f; l_i[i] = 0.f; }
    float oacc[8][4] = {};
    __syncthreads();

    for (int kt = 0; kt < L / BKT; kt++) {
        const int e0 = kt * BKT;
        // load K tile
        for (int i = tid; i < HD * BKT; i += 256) {
            int c = i >> 6, e = i & 63;
            kv_s[c * SQS + e] = kp[(size_t)c * L + e0 + e];
        }
        __syncthreads();
        // scores: s[d][e] = sum_c q[c][d]*k[c][e]; thread (ty,tx) owns d=ty*4+i, e=tx*4+j
        float s[4][4] = {};
        #pragma unroll 8
        for (int c = 0; c < HD; c++) {
            float4 qa = *(const float4*)&q_s[c * SQS + ty * 4];
            float4 kb = *(const float4*)&kv_s[c * SQS + tx * 4];
            float av[4] = {qa.x, qa.y, qa.z, qa.w};
            float bv[4] = {kb.x, kb.y, kb.z, kb.w};
            #pragma unroll
            for (int i = 0; i < 4; i++)
                #pragma unroll
                for (int j = 0; j < 4; j++) s[i][j] += av[i] * bv[j];
        }
        // online softmax per query row (reduce across the 16 tx lanes)
        float alpha[4];
        #pragma unroll
        for (int i = 0; i < 4; i++) {
            float mx = fmaxf(fmaxf(s[i][0], s[i][1]), fmaxf(s[i][2], s[i][3]));
            #pragma unroll
            for (int off = 8; off; off >>= 1)
                mx = fmaxf(mx, __shfl_xor_sync(0xffffffffu, mx, off, 16));
            float mnew = fmaxf(m_i[i], mx);
            alpha[i] = __expf(m_i[i] - mnew);
            float sum = 0.f;
            #pragma unroll
            for (int j = 0; j < 4; j++) { float p = __expf(s[i][j] - mnew); s[i][j] = p; sum += p; }
            #pragma unroll
            for (int off = 8; off; off >>= 1)
                sum += __shfl_xor_sync(0xffffffffu, sum, off, 16);
            l_i[i] = l_i[i] * alpha[i] + sum;
            m_i[i] = mnew;
        }
        // write P transposed (p_s[e][d]) and per-query alpha
        #pragma unroll
        for (int j = 0; j < 4; j++)
            *(float4*)&p_s[(tx * 4 + j) * SQS + ty * 4] =
                make_float4(s[0][j], s[1][j], s[2][j], s[3][j]);
        if (tx == 0) {
            #pragma unroll
            for (int i = 0; i < 4; i++) alpha_s[ty * 4 + i] = alpha[i];
        }
        __syncthreads();  // scores done (kv_s free), p_s/alpha_s visible
        // load V tile into kv_s
        for (int i = tid; i < HD * BKT; i += 256) {
            int c = i >> 6, e = i & 63;
            kv_s[c * SQS + e] = vp[(size_t)c * L + e0 + e];
        }
        __syncthreads();
        // rescale accumulator, then O[c][d] += sum_e V[c][e] * P[d][e]
        float al[4];
        #pragma unroll
        for (int j = 0; j < 4; j++) al[j] = alpha_s[od0 + j];
        #pragma unroll
        for (int i = 0; i < 8; i++)
            #pragma unroll
            for (int j = 0; j < 4; j++) oacc[i][j] *= al[j];
        #pragma unroll 4
        for (int e = 0; e < BKT; e++) {
            float4 pv = *(const float4*)&p_s[e * SQS + od0];
            float pj[4] = {pv.x, pv.y, pv.z, pv.w};
            #pragma unroll
            for (int i = 0; i < 8; i++) {
                float vv = kv_s[(oc0 + i) * SQS + e];
                #pragma unroll
                for (int j = 0; j < 4; j++) oacc[i][j] += vv * pj[j];
            }
        }
        __syncthreads();  // PV done; kv_s & p_s free for next tile
    }
    // finalize: divide by l
    if (tx == 0) {
        #pragma unroll
        for (int i = 0; i < 4; i++) alpha_s[ty * 4 + i] = l_i[i];
    }
    __syncthreads();
    float inv[4];
    #pragma unroll
    for (int j = 0; j < 4; j++) inv[j] = 1.0f / alpha_s[od0 + j];
    float* ap = g_att + ((size_t)b * C + h * HD) * L;
    #pragma unroll
    for (int i = 0; i < 8; i++) {
        int c = oc0 + i;
        float4 o = make_float4(oacc[i][0] * inv[0], oacc[i][1] * inv[1],
                               oacc[i][2] * inv[2], oacc[i][3] * inv[3]);
        *(float4*)&ap[(size_t)c * L + q0 + od0] = o;
    }
}

// ---------------- host ----------------
extern "C" void kernel_launch(void* const* d_in, const int* in_sizes, int n_in,
                              void* d_out, int out_size) {
    const float* x      = (const float*)d_in[0];
    const float* gn_w   = (const float*)d_in[1];
    const float* gn_b   = (const float*)d_in[2];
    const float* w_qkv  = (const float*)d_in[3];
    const float* b_qkv  = (const float*)d_in[4];
    const float* w_proj = (const float*)d_in[5];
    const float* b_proj = (const float*)d_in[6];
    float* out = (float*)d_out;

    float *xn_p, *qkv_p, *att_p;
    cudaGetSymbolAddress((void**)&xn_p, g_xn);
    cudaGetSymbolAddress((void**)&qkv_p, g_qkv);
    cudaGetSymbolAddress((void**)&att_p, g_att);

    // 1) GroupNorm
    groupnorm_kernel<<<dim3(GROUPS, BATCH), 256>>>(x, gn_w, gn_b);

    // 2) QKV: [3C x L] = w_qkv[3C x C] * xn[C x L] + b_qkv
    gemm_kernel<<<dim3(L / BN, (3 * C) / BM, BATCH), 256>>>(
        w_qkv, xn_p, b_qkv, nullptr, qkv_p, 3 * C, L, C);

    // 3) attention
    const int smem = (HD * SQS * 2 + BKT * SQS + BQ) * (int)sizeof(float);  // 87296 B
    cudaFuncSetAttribute(attn_kernel, cudaFuncAttributeMaxDynamicSharedMemorySize, smem);
    attn_kernel<<<dim3(L / BQ, BATCH * NH), 256, smem>>>();

    // 4) proj + residual: out = w_proj[C x C] * att[C x L] + b_proj + x
    gemm_kernel<<<dim3(L / BN, C / BM, BATCH), 256>>>(
        w_proj, att_p, b_proj, x, out, C, L, C);
}

// round 3
// speedup vs baseline: 2.0180x; 2.0180x over previous
#include <cuda_runtime.h>
#include <math.h>
#include <stdint.h>

#define BATCH 2
#define C 512
#define L 4096
#define NH 4
#define HD 128
#define GROUPS 32
#define CPG (C / GROUPS)   // 16
#define EPS 1e-5f

// ---------------- scratch (static device globals; no allocation) ----------------
__device__ float g_xn[(size_t)BATCH * C * L];        // 16 MB
__device__ float g_qkv[(size_t)BATCH * 3 * C * L];   // 48 MB
__device__ float g_att[(size_t)BATCH * C * L];       // 16 MB
__device__ float g_qt[(size_t)BATCH * NH * L * HD];  // 16 MB  Q^T [bh][q][c], tf32, pre-scaled
__device__ float g_kt[(size_t)BATCH * NH * L * HD];  // 16 MB  K^T [bh][key][c], tf32

__device__ __forceinline__ float to_tf32(float x) {
    float r; asm("cvt.rna.tf32.f32 %0, %1;" : "=f"(r) : "f"(x)); return r;
}

// mma.sync m16n8k8 tf32: D += A(row-major 16x8) * B(col-major 8x8)
#define MMA_TF32(d, a, b) \
    asm volatile("mma.sync.aligned.m16n8k8.row.col.f32.tf32.tf32.f32 " \
                 "{%0,%1,%2,%3}, {%4,%5,%6,%7}, {%8,%9}, {%0,%1,%2,%3};" \
                 : "+f"((d)[0]), "+f"((d)[1]), "+f"((d)[2]), "+f"((d)[3]) \
                 : "r"((a).x), "r"((a).y), "r"((a).z), "r"((a).w), \
                   "r"((b).x), "r"((b).y))

// ---------------- GroupNorm ----------------
__global__ void __launch_bounds__(256) groupnorm_kernel(const float* __restrict__ x,
                                                        const float* __restrict__ gw,
                                                        const float* __restrict__ gb) {
    const int g = blockIdx.x, b = blockIdx.y;
    const int tid = threadIdx.x;
    const size_t base = ((size_t)b * C + g * CPG) * L;
    const int SPAN = CPG * L;
    const float4* x4 = (const float4*)(x + base);
    float s = 0.f, ss = 0.f;
    for (int i = tid; i < SPAN / 4; i += 256) {
        float4 v = x4[i];
        s  += v.x + v.y + v.z + v.w;
        ss += v.x * v.x + v.y * v.y + v.z * v.z + v.w * v.w;
    }
    __shared__ float rs[256], rss[256];
    rs[tid] = s; rss[tid] = ss;
    __syncthreads();
    for (int off = 128; off; off >>= 1) {
        if (tid < off) { rs[tid] += rs[tid + off]; rss[tid] += rss[tid + off]; }
        __syncthreads();
    }
    __shared__ float s_mean, s_rstd;
    if (tid == 0) {
        float mean = rs[0] / SPAN;
        float var  = rss[0] / SPAN - mean * mean;
        s_mean = mean;
        s_rstd = rsqrtf(var + EPS);
    }
    __syncthreads();
    const float mean = s_mean, rstd = s_rstd;
    float4* o4 = (float4*)(g_xn + base);
    for (int i = tid; i < SPAN / 4; i += 256) {
        int c = g * CPG + (i >> 10);
        float ga = gw[c] * rstd;
        float be = gb[c] - mean * ga;
        float4 v = x4[i];
        float4 o;
        o.x = v.x * ga + be; o.y = v.y * ga + be;
        o.z = v.z * ga + be; o.w = v.w * ga + be;
        o4[i] = o;
    }
}

// ---------------- generic GEMM (from R1, verified) ----------------
#define BM 64
#define BN 64
#define BKK 16

__global__ void __launch_bounds__(256) gemm_kernel(const float* __restrict__ A,
                                                   const float* __restrict__ Bmat,
                                                   const float* __restrict__ bias,
                                                   const float* __restrict__ resid,
                                                   float* __restrict__ Cout,
                                                   int M, int N, int K) {
    const int bz = blockIdx.z;
    Bmat += (size_t)bz * K * N;
    Cout += (size_t)bz * M * N;
    if (resid) resid += (size_t)bz * M * N;
    const int m0 = blockIdx.y * BM, n0 = blockIdx.x * BN;
    const int tid = threadIdx.x;
    const int tx = tid & 15, ty = tid >> 4;

    __shared__ float As[BKK][BM + 4];
    __shared__ float Bs[BKK][BN];

    float acc[4][4] = {};
    const int a_k = tid & 15, a_m = tid >> 4;
    const int b_n = tid & 63, b_k = tid >> 6;

    for (int k0 = 0; k0 < K; k0 += BKK) {
        #pragma unroll
        for (int r = 0; r < 4; r++)
            As[a_k][a_m + r * 16] = A[(size_t)(m0 + a_m + r * 16) * K + k0 + a_k];
        #pragma unroll
        for (int r = 0; r < 4; r++)
            Bs[b_k + r * 4][b_n] = Bmat[(size_t)(k0 + b_k + r * 4) * N + n0 + b_n];
        __syncthreads();
        #pragma unroll
        for (int k = 0; k < BKK; k++) {
            float4 a  = *(const float4*)&As[k][ty * 4];
            float4 bv = *(const float4*)&Bs[k][tx * 4];
            float av[4] = {a.x, a.y, a.z, a.w};
            float bb[4] = {bv.x, bv.y, bv.z, bv.w};
            #pragma unroll
            for (int i = 0; i < 4; i++)
                #pragma unroll
                for (int j = 0; j < 4; j++) acc[i][j] += av[i] * bb[j];
        }
        __syncthreads();
    }
    #pragma unroll
    for (int i = 0; i < 4; i++) {
        int m = m0 + ty * 4 + i;
        float bia = bias ? bias[m] : 0.f;
        float4 o;
        o.x = acc[i][0] + bia; o.y = acc[i][1] + bia;
        o.z = acc[i][2] + bia; o.w = acc[i][3] + bia;
        size_t off = (size_t)m * N + n0 + tx * 4;
        if (resid) {
            float4 r = *(const float4*)&resid[off];
            o.x += r.x; o.y += r.y; o.z += r.z; o.w += r.w;
        }
        *(float4*)&Cout[off] = o;
    }
}

// ---------------- prep: transpose Q,K to [bh][l][c], cvt to tf32 (Q pre-scaled) ----------------
__global__ void __launch_bounds__(256) transpose_qk_kernel(const float* __restrict__ qkv,
                                                           float* __restrict__ qt,
                                                           float* __restrict__ kt) {
    __shared__ float tq[32][33];
    __shared__ float tk[32][33];
    const int bh = blockIdx.z;
    const int b = bh >> 2, h = bh & 3;
    const float* qsrc = qkv + ((size_t)b * 3 * C + h * HD) * L;
    const float* ksrc = qsrc + (size_t)C * L;
    const int l0 = blockIdx.x * 32, c0 = blockIdx.y * 32;
    const int tx = threadIdx.x, ty = threadIdx.y;  // 32 x 8
    #pragma unroll
    for (int j = 0; j < 32; j += 8) {
        tq[ty + j][tx] = qsrc[(size_t)(c0 + ty + j) * L + l0 + tx];
        tk[ty + j][tx] = ksrc[(size_t)(c0 + ty + j) * L + l0 + tx];
    }
    __syncthreads();
    const float scale = 0.08838834764831845f;  // 1/sqrt(128)
    float* qd = qt + (size_t)bh * L * HD;
    float* kd = kt + (size_t)bh * L * HD;
    #pragma unroll
    for (int j = 0; j < 32; j += 8) {
        qd[(size_t)(l0 + ty + j) * HD + c0 + tx] = to_tf32(tq[tx][ty + j] * scale);
        kd[(size_t)(l0 + ty + j) * HD + c0 + tx] = to_tf32(tk[tx][ty + j]);
    }
}

// ---------------- mma.sync tf32 flash attention ----------------
// CTA: 128 queries, loop 32 key-tiles of 128. 256 threads = 8 warps:
// warp w -> (qi = w>>1 owns 32 queries, kh = w&1 owns key/hd half).
// SMEM (dynamic 192KB): Q frags 64KB | K/P frags 64KB | V frags 64KB.
// Fragment layouts (tf32 m16n8k8):
//   A-frag block (mt,kt): 128 floats; lane l holds float4 at l*4:
//     (r,c),(r+8,c),(r,c+4),(r+8,c+4) with r=l>>2, c=l&3 (rel. to 16x8 tile)
//   B-frag block (kt,nt): 64 floats; lane l holds float2 at l*2:
//     (k,n),(k+4,n) with k=l&3, n=l>>2 (rel. to 8x8 tile)
#define ATT_SMEM (3 * 65536)

__global__ void __launch_bounds__(256) attn_mma_kernel(const float* __restrict__ qt_all,
                                                       const float* __restrict__ kt_all,
                                                       const float* __restrict__ qkv,
                                                       float* __restrict__ att) {
    extern __shared__ float smf[];
    float* Qb  = smf;            // 16384 floats (A-frags, 8 mt x 16 kt)
    float* KPb = Qb + 16384;     // 16384 (K B-frags 16x16, then P A-frags 8x16)
    float* Vb  = KPb + 16384;    // 16384 (V B-frags 16x16)
    __shared__ float lsum_s[2][128];

    const int tid = threadIdx.x, w = tid >> 5, l = tid & 31;
    const int qi = w >> 1, kh = w & 1, hj = kh;
    const int qb = blockIdx.x, bh = blockIdx.y;
    const int b = bh >> 2, h = bh & 3;
    const int q0 = qb * 128;

    const float* qt  = qt_all + ((size_t)bh * L + q0) * HD;
    const float* ktp = kt_all + (size_t)bh * L * HD;
    const float* vp  = qkv + ((size_t)b * 3 * C + 2 * C + h * HD) * L;

    const int lr = l >> 2, lc = l & 3;

    // ---- stage Q fragments once (gather 4 x LDG.32 -> STS.128; 32B-sector perfect) ----
    #pragma unroll 4
    for (int i = 0; i < 16; i++) {
        const int bb = w * 16 + i;
        const int mt = bb >> 4, kt = bb & 15;
        const int q = mt * 16 + lr, c = kt * 8 + lc;
        float4 a;
        a.x = qt[q * HD + c];       a.y = qt[(q + 8) * HD + c];
        a.z = qt[q * HD + c + 4];   a.w = qt[(q + 8) * HD + c + 4];
        *(float4*)(Qb + bb * 128 + l * 4) = a;
    }

    float oacc[2][8][4] = {};
    float lsum[2][2] = {};

    for (int ktile = 0; ktile < 32; ktile++) {
        __syncthreads();  // prev PV done -> KPb/Vb free (iter0: Q staged everywhere after this+next)
        // ---- stage K tile: B-frags (kt=chan, nt=key), 32 blocks per warp ----
        const float* ks = ktp + (size_t)(ktile * 128) * HD;
        #pragma unroll 4
        for (int i = 0; i < 32; i++) {
            const int bb = w * 32 + i;
            const int kt = bb >> 4, nt = bb & 15;
            const int key = nt * 8 + lr, c = kt * 8 + lc;
            float2 v2 = make_float2(ks[key * HD + c], ks[key * HD + c + 4]);
            *(float2*)(KPb + bb * 64 + l * 2) = v2;
        }
        // ---- stage V tile: B-frags (kt=key, nt=hd) ----
        const float* vs = vp + ktile * 128;
        #pragma unroll 4
        for (int i = 0; i < 32; i++) {
            const int bb = w * 32 + i;
            const int kt = bb >> 4, nt = bb & 15;
            const int key = kt * 8 + lc, hd = nt * 8 + lr;
            float2 v2 = make_float2(to_tf32(vs[(size_t)hd * L + key]),
                                    to_tf32(vs[(size_t)hd * L + key + 4]));
            *(float2*)(Vb + bb * 64 + l * 2) = v2;
        }
        __syncthreads();

        // ---- S = Q K^T for this warp's 32q x 64key ----
        float sacc[2][8][4] = {};
        #pragma unroll
        for (int kt = 0; kt < 16; kt++) {
            uint4 A0 = *(const uint4*)(Qb + ((qi * 2 + 0) * 16 + kt) * 128 + l * 4);
            uint4 A1 = *(const uint4*)(Qb + ((qi * 2 + 1) * 16 + kt) * 128 + l * 4);
            #pragma unroll
            for (int nt = 0; nt < 8; nt++) {
                uint2 B = *(const uint2*)(KPb + (kt * 16 + kh * 8 + nt) * 64 + l * 2);
                MMA_TF32(sacc[0][nt], A0, B);
                MMA_TF32(sacc[1][nt], A1, B);
            }
        }
        __syncthreads();  // all K reads complete before P overwrites KPb

        // ---- softmax (no max subtraction; scores bounded ~|2|) + P store as A-frags ----
        #pragma unroll
        for (int mt = 0; mt < 2; mt++) {
            #pragma unroll
            for (int nt = 0; nt < 8; nt++) {
                #pragma unroll
                for (int j = 0; j < 4; j++) {
                    float p = to_tf32(__expf(sacc[mt][nt][j]));
                    lsum[mt][j >> 1] += p;
                    const int qq = qi * 32 + mt * 16 + lr + 8 * (j >> 1);
                    const int kk = kh * 64 + nt * 8 + lc * 2 + (j & 1);
                    const int mtP = qq >> 4, ktP = kk >> 3;
                    const int lP = ((qq & 7) << 2) | (kk & 3);
                    const int jP = 2 * ((kk >> 2) & 1) + ((qq >> 3) & 1);
                    KPb[(mtP * 16 + ktP) * 128 + lP * 4 + jP] = p;
                }
            }
        }
        __syncthreads();

        // ---- O += P V : warp's 32q x 64hd over 128 keys ----
        #pragma unroll
        for (int kt = 0; kt < 16; kt++) {
            uint4 A0 = *(const uint4*)(KPb + ((qi * 2 + 0) * 16 + kt) * 128 + l * 4);
            uint4 A1 = *(const uint4*)(KPb + ((qi * 2 + 1) * 16 + kt) * 128 + l * 4);
            #pragma unroll
            for (int nt = 0; nt < 8; nt++) {
                uint2 B = *(const uint2*)(Vb + (kt * 16 + hj * 8 + nt) * 64 + l * 2);
                MMA_TF32(oacc[0][nt], A0, B);
                MMA_TF32(oacc[1][nt], A1, B);
            }
        }
    }

    // ---- reduce lsum across the 4-lane quads, combine the two key-halves ----
    #pragma unroll
    for (int mt = 0; mt < 2; mt++)
        #pragma unroll
        for (int dr = 0; dr < 2; dr++) {
            float v = lsum[mt][dr];
            v += __shfl_xor_sync(0xffffffffu, v, 1);
            v += __shfl_xor_sync(0xffffffffu, v, 2);
            lsum[mt][dr] = v;
        }
    __syncthreads();
    if (lc == 0) {
        #pragma unroll
        for (int mt = 0; mt < 2; mt++)
            #pragma unroll
            for (int dr = 0; dr < 2; dr++)
                lsum_s[kh][qi * 32 + mt * 16 + lr + 8 * dr] = lsum[mt][dr];
    }
    __syncthreads();

    // ---- normalize, transpose via SMEM [hd][q] (stride 132), coalesced store ----
    float* Ob = Qb;  // 128*132*4 = 67584 B, spills into KPb region (both dead)
    #pragma unroll
    for (int mt = 0; mt < 2; mt++) {
        const int r0 = qi * 32 + mt * 16 + lr;
        const float linv0 = 1.0f / (lsum_s[0][r0] + lsum_s[1][r0]);
        const float linv1 = 1.0f / (lsum_s[0][r0 + 8] + lsum_s[1][r0 + 8]);
        #pragma unroll
        for (int nt = 0; nt < 8; nt++) {
            #pragma unroll
            for (int j = 0; j < 4; j++) {
                const int q  = r0 + 8 * (j >> 1);
                const int hd = hj * 64 + nt * 8 + lc * 2 + (j & 1);
                Ob[hd * 132 + q] = oacc[mt][nt][j] * ((j >> 1) ? linv1 : linv0);
            }
        }
    }
    __syncthreads();
    float* ap = att + ((size_t)b * C + h * HD) * L + q0;
    {
        const int r = tid >> 1, hf = tid & 1;
        #pragma unroll
        for (int i = 0; i < 16; i++)
            *(float4*)(ap + (size_t)r * L + hf * 64 + i * 4) =
                *(const float4*)(Ob + r * 132 + hf * 64 + i * 4);
    }
}

// ---------------- host ----------------
extern "C" void kernel_launch(void* const* d_in, const int* in_sizes, int n_in,
                              void* d_out, int out_size) {
    const float* x      = (const float*)d_in[0];
    const float* gn_w   = (const float*)d_in[1];
    const float* gn_b   = (const float*)d_in[2];
    const float* w_qkv  = (const float*)d_in[3];
    const float* b_qkv  = (const float*)d_in[4];
    const float* w_proj = (const float*)d_in[5];
    const float* b_proj = (const float*)d_in[6];
    float* out = (float*)d_out;

    float *xn_p, *qkv_p, *att_p, *qt_p, *kt_p;
    cudaGetSymbolAddress((void**)&xn_p, g_xn);
    cudaGetSymbolAddress((void**)&qkv_p, g_qkv);
    cudaGetSymbolAddress((void**)&att_p, g_att);
    cudaGetSymbolAddress((void**)&qt_p, g_qt);
    cudaGetSymbolAddress((void**)&kt_p, g_kt);

    // 1) GroupNorm
    groupnorm_kernel<<<dim3(GROUPS, BATCH), 256>>>(x, gn_w, gn_b);

    // 2) QKV GEMM
    gemm_kernel<<<dim3(L / BN, (3 * C) / BM, BATCH), 256>>>(
        w_qkv, xn_p, b_qkv, nullptr, qkv_p, 3 * C, L, C);

    // 3) transpose Q (scaled) / K, cvt tf32
    transpose_qk_kernel<<<dim3(L / 32, HD / 32, BATCH * NH), dim3(32, 8)>>>(qkv_p, qt_p, kt_p);

    // 4) attention (mma.sync tf32)
    cudaFuncSetAttribute(attn_mma_kernel, cudaFuncAttributeMaxDynamicSharedMemorySize, ATT_SMEM);
    attn_mma_kernel<<<dim3(L / 128, BATCH * NH), 256, ATT_SMEM>>>(qt_p, kt_p, qkv_p, att_p);

    // 5) proj + residual
    gemm_kernel<<<dim3(L / BN, C / BM, BATCH), 256>>>(
        w_proj, att_p, b_proj, x, out, C, L, C);
}

// round 4
// speedup vs baseline: 3.7641x; 1.8653x over previous
#include <cuda_runtime.h>
#include <math.h>
#include <stdint.h>

#define BATCH 2
#define C 512
#define L 4096
#define NH 4
#define HD 128
#define GROUPS 32
#define CPG (C / GROUPS)   // 16
#define EPS 1e-5f

// ---------------- scratch (static device globals; no allocation) ----------------
__device__ float g_xn[(size_t)BATCH * C * L];        // 16 MB
__device__ float g_qkv[(size_t)BATCH * 3 * C * L];   // 48 MB
__device__ float g_att[(size_t)BATCH * C * L];       // 16 MB
__device__ float g_qt[(size_t)BATCH * NH * L * HD];  // 16 MB  Q^T [bh][q][c] fp32, pre-scaled
__device__ float g_kt[(size_t)BATCH * NH * L * HD];  // 16 MB  K^T [bh][key][c] fp32
// fragment-packed bf16 operands (per bh: 32 tiles x 32KB)
__device__ uint4 g_qf[(size_t)BATCH * NH * 32 * 2048];   // 8 MB  Q A-frags
__device__ uint2 g_kf[(size_t)BATCH * NH * 32 * 4096];   // 8 MB  K B-frags
__device__ uint2 g_vf[(size_t)BATCH * NH * 32 * 4096];   // 8 MB  V B-frags

__device__ __forceinline__ uint32_t smem_u32(const void* p) {
    uint32_t a;
    asm("{ .reg .u64 t; cvta.to.shared.u64 t, %1; cvt.u32.u64 %0, t; }" : "=r"(a) : "l"(p));
    return a;
}
__device__ __forceinline__ uint32_t pack_bf16x2(float lo, float hi) {
    uint32_t d;
    asm("cvt.rn.bf16x2.f32 %0, %1, %2;" : "=r"(d) : "f"(hi), "f"(lo));  // first src -> high half
    return d;
}
// D(f32) += A(bf16 16x16 row) * B(bf16 16x8 col)
#define MMA_BF16(d, a, b) \
    asm volatile("mma.sync.aligned.m16n8k16.row.col.f32.bf16.bf16.f32 " \
                 "{%0,%1,%2,%3}, {%4,%5,%6,%7}, {%8,%9}, {%0,%1,%2,%3};" \
                 : "+f"((d)[0]), "+f"((d)[1]), "+f"((d)[2]), "+f"((d)[3]) \
                 : "r"((a).x), "r"((a).y), "r"((a).z), "r"((a).w), \
                   "r"((b).x), "r"((b).y))

__device__ __forceinline__ void cp16(uint32_t dst, const void* src) {
    asm volatile("cp.async.cg.shared.global [%0], [%1], 16;" :: "r"(dst), "l"(src));
}
#define CP_COMMIT() asm volatile("cp.async.commit_group;" ::: "memory")
#define CP_WAIT(n)  asm volatile("cp.async.wait_group %0;" :: "n"(n) : "memory")

// ---------------- GroupNorm ----------------
__global__ void __launch_bounds__(256) groupnorm_kernel(const float* __restrict__ x,
                                                        const float* __restrict__ gw,
                                                        const float* __restrict__ gb) {
    const int g = blockIdx.x, b = blockIdx.y;
    const int tid = threadIdx.x;
    const size_t base = ((size_t)b * C + g * CPG) * L;
    const int SPAN = CPG * L;
    const float4* x4 = (const float4*)(x + base);
    float s = 0.f, ss = 0.f;
    for (int i = tid; i < SPAN / 4; i += 256) {
        float4 v = x4[i];
        s  += v.x + v.y + v.z + v.w;
        ss += v.x * v.x + v.y * v.y + v.z * v.z + v.w * v.w;
    }
    __shared__ float rs[256], rss[256];
    rs[tid] = s; rss[tid] = ss;
    __syncthreads();
    for (int off = 128; off; off >>= 1) {
        if (tid < off) { rs[tid] += rs[tid + off]; rss[tid] += rss[tid + off]; }
        __syncthreads();
    }
    __shared__ float s_mean, s_rstd;
    if (tid == 0) {
        float mean = rs[0] / SPAN;
        float var  = rss[0] / SPAN - mean * mean;
        s_mean = mean;
        s_rstd = rsqrtf(var + EPS);
    }
    __syncthreads();
    const float mean = s_mean, rstd = s_rstd;
    float4* o4 = (float4*)(g_xn + base);
    for (int i = tid; i < SPAN / 4; i += 256) {
        int c = g * CPG + (i >> 10);
        float ga = gw[c] * rstd;
        float be = gb[c] - mean * ga;
        float4 v = x4[i];
        float4 o;
        o.x = v.x * ga + be; o.y = v.y * ga + be;
        o.z = v.z * ga + be; o.w = v.w * ga + be;
        o4[i] = o;
    }
}

// ---------------- generic fp32 GEMM (verified R1) ----------------
#define BM 64
#define BN 64
#define BKK 16

__global__ void __launch_bounds__(256) gemm_kernel(const float* __restrict__ A,
                                                   const float* __restrict__ Bmat,
                                                   const float* __restrict__ bias,
                                                   const float* __restrict__ resid,
                                                   float* __restrict__ Cout,
                                                   int M, int N, int K) {
    const int bz = blockIdx.z;
    Bmat += (size_t)bz * K * N;
    Cout += (size_t)bz * M * N;
    if (resid) resid += (size_t)bz * M * N;
    const int m0 = blockIdx.y * BM, n0 = blockIdx.x * BN;
    const int tid = threadIdx.x;
    const int tx = tid & 15, ty = tid >> 4;

    __shared__ float As[BKK][BM + 4];
    __shared__ float Bs[BKK][BN];

    float acc[4][4] = {};
    const int a_k = tid & 15, a_m = tid >> 4;
    const int b_n = tid & 63, b_k = tid >> 6;

    for (int k0 = 0; k0 < K; k0 += BKK) {
        #pragma unroll
        for (int r = 0; r < 4; r++)
            As[a_k][a_m + r * 16] = A[(size_t)(m0 + a_m + r * 16) * K + k0 + a_k];
        #pragma unroll
        for (int r = 0; r < 4; r++)
            Bs[b_k + r * 4][b_n] = Bmat[(size_t)(k0 + b_k + r * 4) * N + n0 + b_n];
        __syncthreads();
        #pragma unroll
        for (int k = 0; k < BKK; k++) {
            float4 a  = *(const float4*)&As[k][ty * 4];
            float4 bv = *(const float4*)&Bs[k][tx * 4];
            float av[4] = {a.x, a.y, a.z, a.w};
            float bb[4] = {bv.x, bv.y, bv.z, bv.w};
            #pragma unroll
            for (int i = 0; i < 4; i++)
                #pragma unroll
                for (int j = 0; j < 4; j++) acc[i][j] += av[i] * bb[j];
        }
        __syncthreads();
    }
    #pragma unroll
    for (int i = 0; i < 4; i++) {
        int m = m0 + ty * 4 + i;
        float bia = bias ? bias[m] : 0.f;
        float4 o;
        o.x = acc[i][0] + bia; o.y = acc[i][1] + bia;
        o.z = acc[i][2] + bia; o.w = acc[i][3] + bia;
        size_t off = (size_t)m * N + n0 + tx * 4;
        if (resid) {
            float4 r = *(const float4*)&resid[off];
            o.x += r.x; o.y += r.y; o.z += r.z; o.w += r.w;
        }
        *(float4*)&Cout[off] = o;
    }
}

// ---------------- transpose Q,K to [bh][l][c] fp32 (Q pre-scaled) ----------------
__global__ void __launch_bounds__(256) transpose_qk_kernel(const float* __restrict__ qkv,
                                                           float* __restrict__ qt,
                                                           float* __restrict__ kt) {
    __shared__ float tq[32][33];
    __shared__ float tk[32][33];
    const int bh = blockIdx.z;
    const int b = bh >> 2, h = bh & 3;
    const float* qsrc = qkv + ((size_t)b * 3 * C + h * HD) * L;
    const float* ksrc = qsrc + (size_t)C * L;
    const int l0 = blockIdx.x * 32, c0 = blockIdx.y * 32;
    const int tx = threadIdx.x, ty = threadIdx.y;  // 32 x 8
    #pragma unroll
    for (int j = 0; j < 32; j += 8) {
        tq[ty + j][tx] = qsrc[(size_t)(c0 + ty + j) * L + l0 + tx];
        tk[ty + j][tx] = ksrc[(size_t)(c0 + ty + j) * L + l0 + tx];
    }
    __syncthreads();
    const float scale = 0.08838834764831845f;  // 1/sqrt(128)
    float* qd = qt + (size_t)bh * L * HD;
    float* kd = kt + (size_t)bh * L * HD;
    #pragma unroll
    for (int j = 0; j < 32; j += 8) {
        qd[(size_t)(l0 + ty + j) * HD + c0 + tx] = tq[tx][ty + j] * scale;
        kd[(size_t)(l0 + ty + j) * HD + c0 + tx] = tk[tx][ty + j];
    }
}

// ---------------- fragment packing (bf16) ----------------
// m16n8k16 A-frag: lane(gid=l>>2,tig=l&3): a0=(gid, 2tig,2tig+1) a1=(gid+8,..) a2=(gid, +8) a3=(gid+8, +8)
// B-frag: b0=(k=2tig,2tig+1, n=gid) b1=(k+8, n=gid)
__global__ void __launch_bounds__(256) pack_q_kernel(const float* __restrict__ qt,
                                                     uint4* __restrict__ qf) {
    const int bh = blockIdx.y;
    const int idx = blockIdx.x * 256 + threadIdx.x;   // 65536 per bh
    const int qtile = idx >> 11, rem = idx & 2047;
    const int blk = rem >> 5, lane = rem & 31;
    const int mtb = blk >> 3, ktc = blk & 7;
    const int gid = lane >> 2, tig = lane & 3;
    const float* r0 = qt + ((size_t)bh * L + qtile * 128 + mtb * 16 + gid) * HD + ktc * 16;
    const float* r8 = r0 + 8 * HD;
    float2 a0 = *(const float2*)(r0 + 2 * tig);
    float2 a1 = *(const float2*)(r8 + 2 * tig);
    float2 a2 = *(const float2*)(r0 + 2 * tig + 8);
    float2 a3 = *(const float2*)(r8 + 2 * tig + 8);
    uint4 o;
    o.x = pack_bf16x2(a0.x, a0.y); o.y = pack_bf16x2(a1.x, a1.y);
    o.z = pack_bf16x2(a2.x, a2.y); o.w = pack_bf16x2(a3.x, a3.y);
    qf[(size_t)bh * 65536 + idx] = o;
}

__global__ void __launch_bounds__(256) pack_k_kernel(const float* __restrict__ kt,
                                                     uint2* __restrict__ kf) {
    const int bh = blockIdx.y;
    const int idx = blockIdx.x * 256 + threadIdx.x;   // 131072 per bh
    const int tile = idx >> 12, rem = idx & 4095;
    const int blk = rem >> 5, lane = rem & 31;
    const int ktc = blk >> 4, ntb = blk & 15;
    const int gid = lane >> 2, tig = lane & 3;
    const float* kr = kt + ((size_t)bh * L + tile * 128 + ntb * 8 + gid) * HD + ktc * 16;
    float2 b0 = *(const float2*)(kr + 2 * tig);
    float2 b1 = *(const float2*)(kr + 2 * tig + 8);
    uint2 o;
    o.x = pack_bf16x2(b0.x, b0.y);
    o.y = pack_bf16x2(b1.x, b1.y);
    kf[(size_t)bh * 131072 + idx] = o;
}

__global__ void __launch_bounds__(256) pack_v_kernel(const float* __restrict__ qkv,
                                                     uint2* __restrict__ vf) {
    const int bh = blockIdx.y;
    const int b = bh >> 2, h = bh & 3;
    const float* vp = qkv + ((size_t)b * 3 * C + 2 * C + h * HD) * L;
    const int idx = blockIdx.x * 256 + threadIdx.x;
    const int tile = idx >> 12, rem = idx & 4095;
    const int blk = rem >> 5, lane = rem & 31;
    const int ktk = blk >> 4, ntb = blk & 15;
    const int gid = lane >> 2, tig = lane & 3;
    const int hd = ntb * 8 + gid;
    const int key0 = tile * 128 + ktk * 16 + 2 * tig;
    const float* vr = vp + (size_t)hd * L + key0;
    float2 b0 = *(const float2*)(vr);
    float2 b1 = *(const float2*)(vr + 8);
    uint2 o;
    o.x = pack_bf16x2(b0.x, b0.y);
    o.y = pack_bf16x2(b1.x, b1.y);
    vf[(size_t)bh * 131072 + idx] = o;
}

// ---------------- bf16 mma flash attention, cp.async double-buffered ----------------
// smem bytes: Q 32K | K0 32K | K1 32K | V0 32K | V1 32K | P 32K = 192KB
#define SM_Q  0
#define SM_K0 32768
#define SM_V0 98304
#define SM_P  163840
#define ATT_SMEM 196608

__global__ void __launch_bounds__(256) attn_bf16_kernel(const uint4* __restrict__ qf,
                                                        const uint2* __restrict__ kf,
                                                        const uint2* __restrict__ vf,
                                                        float* __restrict__ att) {
    extern __shared__ char sm[];
    const uint32_t sb = smem_u32(sm);
    __shared__ float lsum_s[2][128];

    const int tid = threadIdx.x, w = tid >> 5, l = tid & 31;
    const int qi = w >> 1, kh = w & 1;
    const int gid = l >> 2, tig = l & 3;
    const int qb = blockIdx.x, bh = blockIdx.y;
    const int b = bh >> 2, h = bh & 3;

    const char* qsrc = (const char*)(qf + ((size_t)bh * 32 + qb) * 2048);
    const char* ksrc = (const char*)(kf + (size_t)bh * 131072);
    const char* vsrc = (const char*)(vf + (size_t)bh * 131072);

    // prologue: Q + tile0 K/V  (each 32KB = 2048 x 16B)
    #pragma unroll
    for (int j = 0; j < 8; j++) {
        const int i = tid + j * 256;
        cp16(sb + SM_Q + i * 16, qsrc + i * 16);
        cp16(sb + SM_K0 + i * 16, ksrc + i * 16);
        cp16(sb + SM_V0 + i * 16, vsrc + i * 16);
    }
    CP_COMMIT();

    float oacc[2][8][4] = {};
    float lsum[2][2] = {};

    for (int t = 0; t < 32; t++) {
        __syncthreads();  // everyone done with buf[(t+1)&1] (tile t-1) and P
        if (t + 1 < 32) {
            const int pb = (t + 1) & 1;
            const char* kp = ksrc + (size_t)(t + 1) * 32768;
            const char* vp = vsrc + (size_t)(t + 1) * 32768;
            #pragma unroll
            for (int j = 0; j < 8; j++) {
                const int i = tid + j * 256;
                cp16(sb + SM_K0 + pb * 32768 + i * 16, kp + i * 16);
                cp16(sb + SM_V0 + pb * 32768 + i * 16, vp + i * 16);
            }
            CP_COMMIT();
            CP_WAIT(1);   // tile t complete (newest group may still fly)
        } else {
            CP_WAIT(0);
        }
        __syncthreads();  // tile t visible to all

        const uint32_t Kb = sb + SM_K0 + (t & 1) * 32768;
        // ---- S = Q K^T (warp: 32q x 64key) ----
        float sacc[2][8][4] = {};
        #pragma unroll
        for (int ktc = 0; ktc < 8; ktc++) {
            uint4 A0 = *(const uint4*)(sm + SM_Q + (((qi * 2 + 0) * 8 + ktc) * 32 + l) * 16);
            uint4 A1 = *(const uint4*)(sm + SM_Q + (((qi * 2 + 1) * 8 + ktc) * 32 + l) * 16);
            #pragma unroll
            for (int nt = 0; nt < 8; nt++) {
                uint2 B = *(const uint2*)(sm + (Kb - sb) + ((ktc * 16 + kh * 8 + nt) * 32 + l) * 8);
                MMA_BF16(sacc[0][nt], A0, B);
                MMA_BF16(sacc[1][nt], A1, B);
            }
        }

        // ---- softmax (no max subtraction) + pack P directly into A-frag form ----
        #pragma unroll
        for (int mt = 0; mt < 2; mt++) {
            #pragma unroll
            for (int kc = 0; kc < 4; kc++) {
                const int nt0 = 2 * kc, nt1 = 2 * kc + 1;
                float p00 = __expf(sacc[mt][nt0][0]), p01 = __expf(sacc[mt][nt0][1]);
                float p02 = __expf(sacc[mt][nt0][2]), p03 = __expf(sacc[mt][nt0][3]);
                float p10 = __expf(sacc[mt][nt1][0]), p11 = __expf(sacc[mt][nt1][1]);
                float p12 = __expf(sacc[mt][nt1][2]), p13 = __expf(sacc[mt][nt1][3]);
                lsum[mt][0] += p00 + p01 + p10 + p11;
                lsum[mt][1] += p02 + p03 + p12 + p13;
                uint4 o;
                o.x = pack_bf16x2(p00, p01);   // a0: row gid,  k 2tig..+1
                o.y = pack_bf16x2(p02, p03);   // a1: row gid+8
                o.z = pack_bf16x2(p10, p11);   // a2: row gid,  k+8
                o.w = pack_bf16x2(p12, p13);   // a3: row gid+8, k+8
                *(uint4*)(sm + SM_P + (((qi * 2 + mt) * 8 + (kh * 4 + kc)) * 32 + l) * 16) = o;
            }
        }
        __syncthreads();  // P visible

        // ---- O += P V (warp: 32q x 64hd, all 128 keys) ----
        const uint32_t Vb = SM_V0 + (t & 1) * 32768;
        #pragma unroll
        for (int kt = 0; kt < 8; kt++) {
            uint4 A0 = *(const uint4*)(sm + SM_P + (((qi * 2 + 0) * 8 + kt) * 32 + l) * 16);
            uint4 A1 = *(const uint4*)(sm + SM_P + (((qi * 2 + 1) * 8 + kt) * 32 + l) * 16);
            #pragma unroll
            for (int nt = 0; nt < 8; nt++) {
                uint2 B = *(const uint2*)(sm + Vb + ((kt * 16 + kh * 8 + nt) * 32 + l) * 8);
                MMA_BF16(oacc[0][nt], A0, B);
                MMA_BF16(oacc[1][nt], A1, B);
            }
        }
    }

    // ---- lsum: quad-reduce over tig, then combine key-halves via smem ----
    #pragma unroll
    for (int mt = 0; mt < 2; mt++)
        #pragma unroll
        for (int dr = 0; dr < 2; dr++) {
            float v = lsum[mt][dr];
            v += __shfl_xor_sync(0xffffffffu, v, 1);
            v += __shfl_xor_sync(0xffffffffu, v, 2);
            lsum[mt][dr] = v;
        }
    __syncthreads();
    if (tig == 0) {
        #pragma unroll
        for (int mt = 0; mt < 2; mt++)
            #pragma unroll
            for (int dr = 0; dr < 2; dr++)
                lsum_s[kh][qi * 32 + mt * 16 + gid + 8 * dr] = lsum[mt][dr];
    }
    __syncthreads();

    // ---- normalize + transpose to [hd][q] via smem (stride 132), coalesced store ----
    float* Ob = (float*)sm;  // 128*132*4 B over dead Q/K region
    #pragma unroll
    for (int mt = 0; mt < 2; mt++) {
        const int r0 = qi * 32 + mt * 16 + gid;
        const float linv0 = 1.0f / (lsum_s[0][r0] + lsum_s[1][r0]);
        const float linv1 = 1.0f / (lsum_s[0][r0 + 8] + lsum_s[1][r0 + 8]);
        #pragma unroll
        for (int nt = 0; nt < 8; nt++) {
            #pragma unroll
            for (int j = 0; j < 4; j++) {
                const int q  = r0 + 8 * (j >> 1);
                const int hd = kh * 64 + nt * 8 + tig * 2 + (j & 1);
                Ob[hd * 132 + q] = oacc[mt][nt][j] * ((j >> 1) ? linv1 : linv0);
            }
        }
    }
    __syncthreads();
    float* ap = att + ((size_t)b * C + h * HD) * L + qb * 128;
    {
        const int r = tid >> 1, hf = tid & 1;
        #pragma unroll
        for (int i = 0; i < 16; i++)
            *(float4*)(ap + (size_t)r * L + hf * 64 + i * 4) =
                *(const float4*)(Ob + r * 132 + hf * 64 + i * 4);
    }
}

// ---------------- host ----------------
extern "C" void kernel_launch(void* const* d_in, const int* in_sizes, int n_in,
                              void* d_out, int out_size) {
    const float* x      = (const float*)d_in[0];
    const float* gn_w   = (const float*)d_in[1];
    const float* gn_b   = (const float*)d_in[2];
    const float* w_qkv  = (const float*)d_in[3];
    const float* b_qkv  = (const float*)d_in[4];
    const float* w_proj = (const float*)d_in[5];
    const float* b_proj = (const float*)d_in[6];
    float* out = (float*)d_out;

    float *xn_p, *qkv_p, *att_p, *qt_p, *kt_p;
    uint4* qf_p; uint2 *kf_p, *vf_p;
    cudaGetSymbolAddress((void**)&xn_p, g_xn);
    cudaGetSymbolAddress((void**)&qkv_p, g_qkv);
    cudaGetSymbolAddress((void**)&att_p, g_att);
    cudaGetSymbolAddress((void**)&qt_p, g_qt);
    cudaGetSymbolAddress((void**)&kt_p, g_kt);
    cudaGetSymbolAddress((void**)&qf_p, g_qf);
    cudaGetSymbolAddress((void**)&kf_p, g_kf);
    cudaGetSymbolAddress((void**)&vf_p, g_vf);

    // 1) GroupNorm
    groupnorm_kernel<<<dim3(GROUPS, BATCH), 256>>>(x, gn_w, gn_b);

    // 2) QKV GEMM
    gemm_kernel<<<dim3(L / BN, (3 * C) / BM, BATCH), 256>>>(
        w_qkv, xn_p, b_qkv, nullptr, qkv_p, 3 * C, L, C);

    // 3) transpose Q (scaled) / K to [l][c] fp32
    transpose_qk_kernel<<<dim3(L / 32, HD / 32, BATCH * NH), dim3(32, 8)>>>(qkv_p, qt_p, kt_p);

    // 4) pack bf16 fragments
    pack_q_kernel<<<dim3(256, BATCH * NH), 256>>>(qt_p, qf_p);
    pack_k_kernel<<<dim3(512, BATCH * NH), 256>>>(kt_p, kf_p);
    pack_v_kernel<<<dim3(512, BATCH * NH), 256>>>(qkv_p, vf_p);

    // 5) attention (bf16 mma + cp.async pipeline)
    cudaFuncSetAttribute(attn_bf16_kernel, cudaFuncAttributeMaxDynamicSharedMemorySize, ATT_SMEM);
    attn_bf16_kernel<<<dim3(L / 128, BATCH * NH), 256, ATT_SMEM>>>(qf_p, kf_p, vf_p, att_p);

    // 6) proj + residual
    gemm_kernel<<<dim3(L / BN, C / BM, BATCH), 256>>>(
        w_proj, att_p, b_proj, x, out, C, L, C);
}

// round 5
// speedup vs baseline: 8.5775x; 2.2787x over previous
#include <cuda_runtime.h>
#include <math.h>
#include <stdint.h>

#define BATCH 2
#define C 512
#define L 4096
#define NH 4
#define HD 128
#define GROUPS 32
#define CPG (C / GROUPS)   // 16
#define EPS 1e-5f

// ---------------- scratch (static device globals; no allocation) ----------------
__device__ float g_xn[(size_t)BATCH * C * L];        // 16 MB  GN output fp32
__device__ float g_qkv[(size_t)BATCH * 3 * C * L];   // 48 MB  QKV GEMM output fp32
// fragment-packed bf16 operands
__device__ uint4 g_qf[(size_t)BATCH * NH * 32 * 2048];   // 8 MB  Q A-frags (attention)
__device__ uint2 g_kf[(size_t)BATCH * NH * 32 * 4096];   // 8 MB  K B-frags
__device__ uint2 g_vf[(size_t)BATCH * NH * 32 * 4096];   // 8 MB  V B-frags
__device__ uint2 g_xnf[(size_t)BATCH * 512 * 32 * 32];   // 8 MB  xn B-frags (QKV GEMM)
__device__ uint2 g_attf[(size_t)BATCH * 512 * 32 * 32];  // 8 MB  att B-frags (proj GEMM)
__device__ uint4 g_wqf[(size_t)96 * 32 * 32];            // 1.5MB w_qkv A-frags
__device__ uint4 g_wpf[(size_t)32 * 32 * 32];            // 0.5MB w_proj A-frags

__device__ __forceinline__ uint32_t smem_u32(const void* p) {
    uint32_t a;
    asm("{ .reg .u64 t; cvta.to.shared.u64 t, %1; cvt.u32.u64 %0, t; }" : "=r"(a) : "l"(p));
    return a;
}
__device__ __forceinline__ uint32_t pack_bf16x2(float lo, float hi) {
    uint32_t d;
    asm("cvt.rn.bf16x2.f32 %0, %1, %2;" : "=r"(d) : "f"(hi), "f"(lo));  // first src -> high half
    return d;
}
#define MMA_BF16(d, a, b) \
    asm volatile("mma.sync.aligned.m16n8k16.row.col.f32.bf16.bf16.f32 " \
                 "{%0,%1,%2,%3}, {%4,%5,%6,%7}, {%8,%9}, {%0,%1,%2,%3};" \
                 : "+f"((d)[0]), "+f"((d)[1]), "+f"((d)[2]), "+f"((d)[3]) \
                 : "r"((a).x), "r"((a).y), "r"((a).z), "r"((a).w), \
                   "r"((b).x), "r"((b).y))

__device__ __forceinline__ void cp16(uint32_t dst, const void* src) {
    asm volatile("cp.async.cg.shared.global [%0], [%1], 16;" :: "r"(dst), "l"(src));
}
#define CP_COMMIT() asm volatile("cp.async.commit_group;" ::: "memory")
#define CP_WAIT(n)  asm volatile("cp.async.wait_group %0;" :: "n"(n) : "memory")

// ---------------- GroupNorm ----------------
__global__ void __launch_bounds__(256) groupnorm_kernel(const float* __restrict__ x,
                                                        const float* __restrict__ gw,
                                                        const float* __restrict__ gb) {
    const int g = blockIdx.x, b = blockIdx.y;
    const int tid = threadIdx.x;
    const size_t base = ((size_t)b * C + g * CPG) * L;
    const int SPAN = CPG * L;
    const float4* x4 = (const float4*)(x + base);
    float s = 0.f, ss = 0.f;
    for (int i = tid; i < SPAN / 4; i += 256) {
        float4 v = x4[i];
        s  += v.x + v.y + v.z + v.w;
        ss += v.x * v.x + v.y * v.y + v.z * v.z + v.w * v.w;
    }
    __shared__ float rs[256], rss[256];
    rs[tid] = s; rss[tid] = ss;
    __syncthreads();
    for (int off = 128; off; off >>= 1) {
        if (tid < off) { rs[tid] += rs[tid + off]; rss[tid] += rss[tid + off]; }
        __syncthreads();
    }
    __shared__ float s_mean, s_rstd;
    if (tid == 0) {
        float mean = rs[0] / SPAN;
        float var  = rss[0] / SPAN - mean * mean;
        s_mean = mean;
        s_rstd = rsqrtf(var + EPS);
    }
    __syncthreads();
    const float mean = s_mean, rstd = s_rstd;
    float4* o4 = (float4*)(g_xn + base);
    for (int i = tid; i < SPAN / 4; i += 256) {
        int c = g * CPG + (i >> 10);
        float ga = gw[c] * rstd;
        float be = gb[c] - mean * ga;
        float4 v = x4[i];
        float4 o;
        o.x = v.x * ga + be; o.y = v.y * ga + be;
        o.z = v.z * ga + be; o.w = v.w * ga + be;
        o4[i] = o;
    }
}

// ---------------- weight packing: W[M][512] fp32 -> A-frags [mt][kt=32] ----------------
__global__ void __launch_bounds__(256) pack_w_kernel(const float* __restrict__ W,
                                                     uint4* __restrict__ Wf) {
    const int idx = blockIdx.x * 256 + threadIdx.x;
    const int blk = idx >> 5, lane = idx & 31;
    const int mt = blk >> 5, kt = blk & 31;
    const int gid = lane >> 2, tig = lane & 3;
    const float* r0 = W + (size_t)(mt * 16 + gid) * 512 + kt * 16;
    const float* r8 = r0 + 8 * 512;
    float2 a0 = *(const float2*)(r0 + 2 * tig);
    float2 a1 = *(const float2*)(r8 + 2 * tig);
    float2 a2 = *(const float2*)(r0 + 2 * tig + 8);
    float2 a3 = *(const float2*)(r8 + 2 * tig + 8);
    uint4 o;
    o.x = pack_bf16x2(a0.x, a0.y); o.y = pack_bf16x2(a1.x, a1.y);
    o.z = pack_bf16x2(a2.x, a2.y); o.w = pack_bf16x2(a3.x, a3.y);
    Wf[idx] = o;
}

// ---------------- xn packing: xn[b][c][l] -> B-frags [b][nt=512][kt=32] ----------------
__global__ void __launch_bounds__(256) pack_xn_kernel(const float* __restrict__ xn,
                                                      uint2* __restrict__ Bf) {
    const int b = blockIdx.y;
    const int idx = blockIdx.x * 256 + threadIdx.x;   // 524288 per batch
    const int blk = idx >> 5, lane = idx & 31;
    const int nt = blk >> 5, kt = blk & 31;
    const int gid = lane >> 2, tig = lane & 3;
    const int n = nt * 8 + gid;
    const int c0 = kt * 16 + 2 * tig;
    const float* src = xn + (size_t)b * C * L;
    uint2 o;
    o.x = pack_bf16x2(src[(size_t)c0 * L + n],       src[(size_t)(c0 + 1) * L + n]);
    o.y = pack_bf16x2(src[(size_t)(c0 + 8) * L + n], src[(size_t)(c0 + 9) * L + n]);
    Bf[(size_t)b * 524288 + idx] = o;
}

// ---------------- bf16 tensor-core GEMM ----------------
// out[b][m][n] = sum_k W[m][k] * B[b][k][n] + bias[m] (+ resid[b][m][n])
// A-frags: Af[(mt*32+kt)*32 + lane] uint4.  B-frags: Bf[b][ (nt*32+kt)*32 + lane ] uint2.
// CTA: 128m x 128n. 8 warps: mi=w>>1 (32 rows), nh=w&1 (64 cols). K=512 in 16 chunks of 32.
__global__ void __launch_bounds__(256) gemm_bf16_kernel(const uint4* __restrict__ Af,
                                                        const uint2* __restrict__ Bf,
                                                        const float* __restrict__ bias,
                                                        const float* __restrict__ resid,
                                                        float* __restrict__ out, int M) {
    __shared__ char smbuf[32768];   // 2 stages x (A 8KB + B 8KB)
    const uint32_t sb = smem_u32(smbuf);
    const int tid = threadIdx.x, w = tid >> 5, l = tid & 31;
    const int mi = w >> 1, nh = w & 1, gid = l >> 2, tig = l & 3;
    const int nb = blockIdx.x, mb = blockIdx.y, bz = blockIdx.z;
    Bf += (size_t)bz * 524288;
    out += (size_t)bz * M * L;
    if (resid) resid += (size_t)bz * M * L;

    auto issue = [&](int kc, int s) {
        #pragma unroll
        for (int j = 0; j < 2; j++) {          // A: 512 x 16B
            const int e = tid + j * 256;
            const int bl = e >> 5, ln = e & 31;    // bl = i*2+ktl
            const int i = bl >> 1, ktl = bl & 1;
            cp16(sb + s * 16384 + e * 16,
                 (const char*)(Af + ((size_t)(mb * 8 + i) * 32 + kc * 2 + ktl) * 32 + ln));
        }
        #pragma unroll
        for (int j = 0; j < 2; j++) {          // B: 512 x 16B
            const int f = tid + j * 256;
            const int bl = f >> 4, lp = f & 15;    // bl = nt*2+ktl
            const int nt = bl >> 1, ktl = bl & 1;
            cp16(sb + s * 16384 + 8192 + bl * 256 + lp * 16,
                 (const char*)Bf + ((size_t)(nb * 16 + nt) * 32 + kc * 2 + ktl) * 256 + lp * 16);
        }
    };

    issue(0, 0); CP_COMMIT();
    float acc[2][8][4] = {};
    for (int t = 0; t < 16; t++) {
        if (t + 1 < 16) { issue(t + 1, (t + 1) & 1); CP_COMMIT(); CP_WAIT(1); }
        else            { CP_WAIT(0); }
        __syncthreads();
        const int s = t & 1;
        #pragma unroll
        for (int ktl = 0; ktl < 2; ktl++) {
            uint4 A0 = *(const uint4*)(smbuf + s * 16384 + (((mi * 2 + 0) * 2 + ktl) * 32 + l) * 16);
            uint4 A1 = *(const uint4*)(smbuf + s * 16384 + (((mi * 2 + 1) * 2 + ktl) * 32 + l) * 16);
            #pragma unroll
            for (int nt = 0; nt < 8; nt++) {
                uint2 B = *(const uint2*)(smbuf + s * 16384 + 8192 + (((nh * 8 + nt) * 2 + ktl) * 32 + l) * 8);
                MMA_BF16(acc[0][nt], A0, B);
                MMA_BF16(acc[1][nt], A1, B);
            }
        }
        __syncthreads();   // buf s free before it is re-issued
    }

    #pragma unroll
    for (int r = 0; r < 2; r++) {
        const int m0 = mb * 128 + mi * 32 + r * 16 + gid;
        const float b0v = bias[m0], b8v = bias[m0 + 8];
        #pragma unroll
        for (int nt = 0; nt < 8; nt++) {
            const int n0 = nb * 128 + nh * 64 + nt * 8 + 2 * tig;
            const size_t o0 = (size_t)m0 * L + n0, o8 = (size_t)(m0 + 8) * L + n0;
            float2 v0 = make_float2(acc[r][nt][0] + b0v, acc[r][nt][1] + b0v);
            float2 v8 = make_float2(acc[r][nt][2] + b8v, acc[r][nt][3] + b8v);
            if (resid) {
                float2 r0 = *(const float2*)(resid + o0);
                float2 r8 = *(const float2*)(resid + o8);
                v0.x += r0.x; v0.y += r0.y; v8.x += r8.x; v8.y += r8.y;
            }
            *(float2*)(out + o0) = v0;
            *(float2*)(out + o8) = v8;
        }
    }
}

// ---------------- attention fragment packing (from g_qkv, [c][l] layout) ----------------
__global__ void __launch_bounds__(256) pack_q_kernel(const float* __restrict__ qkv,
                                                     uint4* __restrict__ qf) {
    const int bh = blockIdx.y;
    const int b = bh >> 2, h = bh & 3;
    const float* qs = qkv + ((size_t)b * 3 * C + h * HD) * L;
    const int idx = blockIdx.x * 256 + threadIdx.x;   // 65536 per bh
    const int qtile = idx >> 11, rem = idx & 2047;
    const int blk = rem >> 5, lane = rem & 31;
    const int mtb = blk >> 3, ktc = blk & 7;
    const int gid = lane >> 2, tig = lane & 3;
    const int q = qtile * 128 + mtb * 16 + gid;
    const int c0 = ktc * 16 + 2 * tig;
    const float s = 0.08838834764831845f;  // 1/sqrt(128)
    uint4 o;
    o.x = pack_bf16x2(s * qs[(size_t)c0 * L + q],           s * qs[(size_t)(c0 + 1) * L + q]);
    o.y = pack_bf16x2(s * qs[(size_t)c0 * L + q + 8],       s * qs[(size_t)(c0 + 1) * L + q + 8]);
    o.z = pack_bf16x2(s * qs[(size_t)(c0 + 8) * L + q],     s * qs[(size_t)(c0 + 9) * L + q]);
    o.w = pack_bf16x2(s * qs[(size_t)(c0 + 8) * L + q + 8], s * qs[(size_t)(c0 + 9) * L + q + 8]);
    qf[(size_t)bh * 65536 + idx] = o;
}

__global__ void __launch_bounds__(256) pack_k_kernel(const float* __restrict__ qkv,
                                                     uint2* __restrict__ kf) {
    const int bh = blockIdx.y;
    const int b = bh >> 2, h = bh & 3;
    const float* ks = qkv + ((size_t)b * 3 * C + C + h * HD) * L;
    const int idx = blockIdx.x * 256 + threadIdx.x;   // 131072 per bh
    const int tile = idx >> 12, rem = idx & 4095;
    const int blk = rem >> 5, lane = rem & 31;
    const int ktc = blk >> 4, ntb = blk & 15;
    const int gid = lane >> 2, tig = lane & 3;
    const int key = tile * 128 + ntb * 8 + gid;
    const int c0 = ktc * 16 + 2 * tig;
    uint2 o;
    o.x = pack_bf16x2(ks[(size_t)c0 * L + key],       ks[(size_t)(c0 + 1) * L + key]);
    o.y = pack_bf16x2(ks[(size_t)(c0 + 8) * L + key], ks[(size_t)(c0 + 9) * L + key]);
    kf[(size_t)bh * 131072 + idx] = o;
}

__global__ void __launch_bounds__(256) pack_v_kernel(const float* __restrict__ qkv,
                                                     uint2* __restrict__ vf) {
    const int bh = blockIdx.y;
    const int b = bh >> 2, h = bh & 3;
    const float* vp = qkv + ((size_t)b * 3 * C + 2 * C + h * HD) * L;
    const int idx = blockIdx.x * 256 + threadIdx.x;
    const int tile = idx >> 12, rem = idx & 4095;
    const int blk = rem >> 5, lane = rem & 31;
    const int ktk = blk >> 4, ntb = blk & 15;
    const int gid = lane >> 2, tig = lane & 3;
    const int hd = ntb * 8 + gid;
    const int key0 = tile * 128 + ktk * 16 + 2 * tig;
    const float* vr = vp + (size_t)hd * L + key0;
    float2 b0 = *(const float2*)(vr);
    float2 b1 = *(const float2*)(vr + 8);
    uint2 o;
    o.x = pack_bf16x2(b0.x, b0.y);
    o.y = pack_bf16x2(b1.x, b1.y);
    vf[(size_t)bh * 131072 + idx] = o;
}

// ---------------- bf16 mma flash attention, cp.async double-buffered ----------------
// smem bytes: Q 32K | K0 32K | K1 32K | V0 32K | V1 32K | P 32K = 192KB
#define SM_Q  0
#define SM_K0 32768
#define SM_V0 98304
#define SM_P  163840
#define ATT_SMEM 196608

__global__ void __launch_bounds__(256) attn_bf16_kernel(const uint4* __restrict__ qf,
                                                        const uint2* __restrict__ kf,
                                                        const uint2* __restrict__ vf,
                                                        uint2* __restrict__ attf) {
    extern __shared__ char sm[];
    const uint32_t sb = smem_u32(sm);
    __shared__ float lsum_s[2][128];

    const int tid = threadIdx.x, w = tid >> 5, l = tid & 31;
    const int qi = w >> 1, kh = w & 1;
    const int gid = l >> 2, tig = l & 3;
    const int qb = blockIdx.x, bh = blockIdx.y;
    const int b = bh >> 2, h = bh & 3;

    const char* qsrc = (const char*)(qf + ((size_t)bh * 32 + qb) * 2048);
    const char* ksrc = (const char*)(kf + (size_t)bh * 131072);
    const char* vsrc = (const char*)(vf + (size_t)bh * 131072);

    #pragma unroll
    for (int j = 0; j < 8; j++) {
        const int i = tid + j * 256;
        cp16(sb + SM_Q + i * 16, qsrc + i * 16);
        cp16(sb + SM_K0 + i * 16, ksrc + i * 16);
        cp16(sb + SM_V0 + i * 16, vsrc + i * 16);
    }
    CP_COMMIT();

    float oacc[2][8][4] = {};
    float lsum[2][2] = {};

    for (int t = 0; t < 32; t++) {
        __syncthreads();
        if (t + 1 < 32) {
            const int pb = (t + 1) & 1;
            const char* kp = ksrc + (size_t)(t + 1) * 32768;
            const char* vp = vsrc + (size_t)(t + 1) * 32768;
            #pragma unroll
            for (int j = 0; j < 8; j++) {
                const int i = tid + j * 256;
                cp16(sb + SM_K0 + pb * 32768 + i * 16, kp + i * 16);
                cp16(sb + SM_V0 + pb * 32768 + i * 16, vp + i * 16);
            }
            CP_COMMIT();
            CP_WAIT(1);
        } else {
            CP_WAIT(0);
        }
        __syncthreads();

        const uint32_t Kb = SM_K0 + (t & 1) * 32768;
        float sacc[2][8][4] = {};
        #pragma unroll
        for (int ktc = 0; ktc < 8; ktc++) {
            uint4 A0 = *(const uint4*)(sm + SM_Q + (((qi * 2 + 0) * 8 + ktc) * 32 + l) * 16);
            uint4 A1 = *(const uint4*)(sm + SM_Q + (((qi * 2 + 1) * 8 + ktc) * 32 + l) * 16);
            #pragma unroll
            for (int nt = 0; nt < 8; nt++) {
                uint2 B = *(const uint2*)(sm + Kb + ((ktc * 16 + kh * 8 + nt) * 32 + l) * 8);
                MMA_BF16(sacc[0][nt], A0, B);
                MMA_BF16(sacc[1][nt], A1, B);
            }
        }

        // softmax (no max subtraction) + pack P directly into A-frag form
        #pragma unroll
        for (int mt = 0; mt < 2; mt++) {
            #pragma unroll
            for (int kc = 0; kc < 4; kc++) {
                const int nt0 = 2 * kc, nt1 = 2 * kc + 1;
                float p00 = __expf(sacc[mt][nt0][0]), p01 = __expf(sacc[mt][nt0][1]);
                float p02 = __expf(sacc[mt][nt0][2]), p03 = __expf(sacc[mt][nt0][3]);
                float p10 = __expf(sacc[mt][nt1][0]), p11 = __expf(sacc[mt][nt1][1]);
                float p12 = __expf(sacc[mt][nt1][2]), p13 = __expf(sacc[mt][nt1][3]);
                lsum[mt][0] += p00 + p01 + p10 + p11;
                lsum[mt][1] += p02 + p03 + p12 + p13;
                uint4 o;
                o.x = pack_bf16x2(p00, p01);
                o.y = pack_bf16x2(p02, p03);
                o.z = pack_bf16x2(p10, p11);
                o.w = pack_bf16x2(p12, p13);
                *(uint4*)(sm + SM_P + (((qi * 2 + mt) * 8 + (kh * 4 + kc)) * 32 + l) * 16) = o;
            }
        }
        __syncthreads();

        const uint32_t Vb = SM_V0 + (t & 1) * 32768;
        #pragma unroll
        for (int kt = 0; kt < 8; kt++) {
            uint4 A0 = *(const uint4*)(sm + SM_P + (((qi * 2 + 0) * 8 + kt) * 32 + l) * 16);
            uint4 A1 = *(const uint4*)(sm + SM_P + (((qi * 2 + 1) * 8 + kt) * 32 + l) * 16);
            #pragma unroll
            for (int nt = 0; nt < 8; nt++) {
                uint2 B = *(const uint2*)(sm + Vb + ((kt * 16 + kh * 8 + nt) * 32 + l) * 8);
                MMA_BF16(oacc[0][nt], A0, B);
                MMA_BF16(oacc[1][nt], A1, B);
            }
        }
    }

    // lsum: quad-reduce over tig, combine key-halves via smem
    #pragma unroll
    for (int mt = 0; mt < 2; mt++)
        #pragma unroll
        for (int dr = 0; dr < 2; dr++) {
            float v = lsum[mt][dr];
            v += __shfl_xor_sync(0xffffffffu, v, 1);
            v += __shfl_xor_sync(0xffffffffu, v, 2);
            lsum[mt][dr] = v;
        }
    __syncthreads();
    if (tig == 0) {
        #pragma unroll
        for (int mt = 0; mt < 2; mt++)
            #pragma unroll
            for (int dr = 0; dr < 2; dr++)
                lsum_s[kh][qi * 32 + mt * 16 + gid + 8 * dr] = lsum[mt][dr];
    }
    __syncthreads();

    // normalize + transpose to Ob[hd][q] (stride 132)
    float* Ob = (float*)sm;
    #pragma unroll
    for (int mt = 0; mt < 2; mt++) {
        const int r0 = qi * 32 + mt * 16 + gid;
        const float linv0 = 1.0f / (lsum_s[0][r0] + lsum_s[1][r0]);
        const float linv1 = 1.0f / (lsum_s[0][r0 + 8] + lsum_s[1][r0 + 8]);
        #pragma unroll
        for (int nt = 0; nt < 8; nt++) {
            #pragma unroll
            for (int j = 0; j < 4; j++) {
                const int q  = r0 + 8 * (j >> 1);
                const int hd = kh * 64 + nt * 8 + tig * 2 + (j & 1);
                Ob[hd * 132 + q] = oacc[mt][nt][j] * ((j >> 1) ? linv1 : linv0);
            }
        }
    }
    __syncthreads();

    // emit proj B-frags directly: att[c][l] B-frag blocks [nt_glob][kt_glob=32]
    const size_t attbase = (size_t)b * 524288;
    #pragma unroll
    for (int it = 0; it < 16; it++) {
        const int slot = tid + it * 256;
        const int lb = slot >> 5, ln = slot & 31;
        const int ntl = lb >> 3, ktl = lb & 7;
        const int g2 = ln >> 2, t2 = ln & 3;
        const int cl = ktl * 16 + 2 * t2;
        const int ql = ntl * 8 + g2;
        uint2 o;
        o.x = pack_bf16x2(Ob[cl * 132 + ql],       Ob[(cl + 1) * 132 + ql]);
        o.y = pack_bf16x2(Ob[(cl + 8) * 132 + ql], Ob[(cl + 9) * 132 + ql]);
        attf[attbase + ((size_t)(qb * 16 + ntl) * 32 + (h * 8 + ktl)) * 32 + ln] = o;
    }
}

// ---------------- host ----------------
extern "C" void kernel_launch(void* const* d_in, const int* in_sizes, int n_in,
                              void* d_out, int out_size) {
    const float* x      = (const float*)d_in[0];
    const float* gn_w   = (const float*)d_in[1];
    const float* gn_b   = (const float*)d_in[2];
    const float* w_qkv  = (const float*)d_in[3];
    const float* b_qkv  = (const float*)d_in[4];
    const float* w_proj = (const float*)d_in[5];
    const float* b_proj = (const float*)d_in[6];
    float* out = (float*)d_out;

    float *xn_p, *qkv_p;
    uint4 *qf_p, *wqf_p, *wpf_p;
    uint2 *kf_p, *vf_p, *xnf_p, *attf_p;
    cudaGetSymbolAddress((void**)&xn_p, g_xn);
    cudaGetSymbolAddress((void**)&qkv_p, g_qkv);
    cudaGetSymbolAddress((void**)&qf_p, g_qf);
    cudaGetSymbolAddress((void**)&kf_p, g_kf);
    cudaGetSymbolAddress((void**)&vf_p, g_vf);
    cudaGetSymbolAddress((void**)&xnf_p, g_xnf);
    cudaGetSymbolAddress((void**)&attf_p, g_attf);
    cudaGetSymbolAddress((void**)&wqf_p, g_wqf);
    cudaGetSymbolAddress((void**)&wpf_p, g_wpf);

    // 1) GroupNorm + operand packing
    groupnorm_kernel<<<dim3(GROUPS, BATCH), 256>>>(x, gn_w, gn_b);
    pack_w_kernel<<<384, 256>>>(w_qkv, wqf_p);    // 96 mt
    pack_w_kernel<<<128, 256>>>(w_proj, wpf_p);   // 32 mt
    pack_xn_kernel<<<dim3(2048, BATCH), 256>>>(xn_p, xnf_p);

    // 2) QKV GEMM (bf16 mma): qkv[b][3C][L]
    gemm_bf16_kernel<<<dim3(32, 12, BATCH), 256>>>(wqf_p, xnf_p, b_qkv, nullptr, qkv_p, 3 * C);

    // 3) pack attention fragments from qkv
    pack_q_kernel<<<dim3(256, BATCH * NH), 256>>>(qkv_p, qf_p);
    pack_k_kernel<<<dim3(512, BATCH * NH), 256>>>(qkv_p, kf_p);
    pack_v_kernel<<<dim3(512, BATCH * NH), 256>>>(qkv_p, vf_p);

    // 4) attention (bf16 mma), emits proj B-frags
    cudaFuncSetAttribute(attn_bf16_kernel, cudaFuncAttributeMaxDynamicSharedMemorySize, ATT_SMEM);
    attn_bf16_kernel<<<dim3(L / 128, BATCH * NH), 256, ATT_SMEM>>>(qf_p, kf_p, vf_p, attf_p);

    // 5) proj GEMM (bf16 mma) + bias + residual -> out
    gemm_bf16_kernel<<<dim3(32, 4, BATCH), 256>>>(wpf_p, attf_p, b_proj, x, out, C);
}

// round 6
// speedup vs baseline: 9.0148x; 1.0510x over previous
#include <cuda_runtime.h>
#include <math.h>
#include <stdint.h>

#define BATCH 2
#define C 512
#define L 4096
#define NH 4
#define HD 128
#define GROUPS 32
#define CPG (C / GROUPS)   // 16
#define EPS 1e-5f

// ---------------- scratch (static device globals; no allocation) ----------------
// fragment-packed bf16 operands
__device__ uint4 g_qf[(size_t)BATCH * NH * 32 * 2048];   // 8 MB  Q A-frags (attention)
__device__ uint2 g_kf[(size_t)BATCH * NH * 32 * 4096];   // 8 MB  K B-frags
__device__ uint2 g_vf[(size_t)BATCH * NH * 32 * 4096];   // 8 MB  V B-frags
__device__ uint2 g_xnf[(size_t)BATCH * 512 * 32 * 32];   // 8 MB  xn B-frags (QKV GEMM)
__device__ uint2 g_attf[(size_t)BATCH * 512 * 32 * 32];  // 8 MB  att B-frags (proj GEMM)
__device__ uint4 g_wqf[(size_t)96 * 32 * 32];            // 1.5MB w_qkv A-frags
__device__ uint4 g_wpf[(size_t)32 * 32 * 32];            // 0.5MB w_proj A-frags

__device__ __forceinline__ uint32_t smem_u32(const void* p) {
    uint32_t a;
    asm("{ .reg .u64 t; cvta.to.shared.u64 t, %1; cvt.u32.u64 %0, t; }" : "=r"(a) : "l"(p));
    return a;
}
__device__ __forceinline__ uint32_t pack_bf16x2(float lo, float hi) {
    uint32_t d;
    asm("cvt.rn.bf16x2.f32 %0, %1, %2;" : "=r"(d) : "f"(hi), "f"(lo));  // first src -> high half
    return d;
}
#define MMA_BF16(d, a, b) \
    asm volatile("mma.sync.aligned.m16n8k16.row.col.f32.bf16.bf16.f32 " \
                 "{%0,%1,%2,%3}, {%4,%5,%6,%7}, {%8,%9}, {%0,%1,%2,%3};" \
                 : "+f"((d)[0]), "+f"((d)[1]), "+f"((d)[2]), "+f"((d)[3]) \
                 : "r"((a).x), "r"((a).y), "r"((a).z), "r"((a).w), \
                   "r"((b).x), "r"((b).y))

__device__ __forceinline__ void cp16(uint32_t dst, const void* src) {
    asm volatile("cp.async.cg.shared.global [%0], [%1], 16;" :: "r"(dst), "l"(src));
}
#define CP_COMMIT() asm volatile("cp.async.commit_group;" ::: "memory")
#define CP_WAIT(n)  asm volatile("cp.async.wait_group %0;" :: "n"(n) : "memory")

// ---------------- GroupNorm fused with xn fragment packing ----------------
// block (g, b): stats over 16ch x 4096, then emit B-frags for kt=g directly.
__global__ void __launch_bounds__(256) groupnorm_pack_kernel(const float* __restrict__ x,
                                                             const float* __restrict__ gw,
                                                             const float* __restrict__ gb,
                                                             uint2* __restrict__ Bf) {
    const int g = blockIdx.x, b = blockIdx.y;
    const int tid = threadIdx.x;
    const size_t base = ((size_t)b * C + g * CPG) * L;
    const int SPAN = CPG * L;
    const float* xr = x + base;
    const float4* x4 = (const float4*)xr;
    float s = 0.f, ss = 0.f;
    for (int i = tid; i < SPAN / 4; i += 256) {
        float4 v = x4[i];
        s  += v.x + v.y + v.z + v.w;
        ss += v.x * v.x + v.y * v.y + v.z * v.z + v.w * v.w;
    }
    __shared__ float rs[256], rss[256];
    rs[tid] = s; rss[tid] = ss;
    __syncthreads();
    for (int off = 128; off; off >>= 1) {
        if (tid < off) { rs[tid] += rs[tid + off]; rss[tid] += rss[tid + off]; }
        __syncthreads();
    }
    __shared__ float ga_s[CPG], be_s[CPG];
    if (tid < CPG) {
        float mean = rs[0] / SPAN;
        float var  = rss[0] / SPAN - mean * mean;
        float rstd = rsqrtf(var + EPS);
        float ga = gw[g * CPG + tid] * rstd;
        ga_s[tid] = ga;
        be_s[tid] = gb[g * CPG + tid] - mean * ga;
    }
    __syncthreads();

    // emit B-frags: Bf[b][(nt*32 + g)*32 + lane], nt = 0..511
    uint2* dst = Bf + (size_t)b * 524288 + (size_t)g * 32;
    for (int i = tid; i < 16384; i += 256) {
        const int nt = i >> 5, lane = i & 31;
        const int gid = lane >> 2, tig = lane & 3;
        const int n = nt * 8 + gid;
        const int lc = 2 * tig;
        float v0 = xr[(size_t)lc * L + n]       * ga_s[lc]     + be_s[lc];
        float v1 = xr[(size_t)(lc + 1) * L + n] * ga_s[lc + 1] + be_s[lc + 1];
        float v8 = xr[(size_t)(lc + 8) * L + n] * ga_s[lc + 8] + be_s[lc + 8];
        float v9 = xr[(size_t)(lc + 9) * L + n] * ga_s[lc + 9] + be_s[lc + 9];
        uint2 o;
        o.x = pack_bf16x2(v0, v1);
        o.y = pack_bf16x2(v8, v9);
        dst[(size_t)nt * 1024 + lane] = o;
    }
}

// ---------------- weight packing: W[M][512] fp32 -> A-frags [mt][kt=32] ----------------
__global__ void __launch_bounds__(256) pack_w_kernel(const float* __restrict__ W,
                                                     uint4* __restrict__ Wf) {
    const int idx = blockIdx.x * 256 + threadIdx.x;
    const int blk = idx >> 5, lane = idx & 31;
    const int mt = blk >> 5, kt = blk & 31;
    const int gid = lane >> 2, tig = lane & 3;
    const float* r0 = W + (size_t)(mt * 16 + gid) * 512 + kt * 16;
    const float* r8 = r0 + 8 * 512;
    float2 a0 = *(const float2*)(r0 + 2 * tig);
    float2 a1 = *(const float2*)(r8 + 2 * tig);
    float2 a2 = *(const float2*)(r0 + 2 * tig + 8);
    float2 a3 = *(const float2*)(r8 + 2 * tig + 8);
    uint4 o;
    o.x = pack_bf16x2(a0.x, a0.y); o.y = pack_bf16x2(a1.x, a1.y);
    o.z = pack_bf16x2(a2.x, a2.y); o.w = pack_bf16x2(a3.x, a3.y);
    Wf[idx] = o;
}

// ---------------- QKV GEMM (bf16 mma) with fused q/k/v fragment epilogue ----------------
// CTA: 128m x 128n; mb 0..11 -> sec = mb>>2 (q/k/v), head = mb&3; nb = l-tile.
// Dynamic smem: staging 32KB (mainloop) overlapped with T[128][130] fp32 (epilogue).
#define QKV_SMEM 66560

__global__ void __launch_bounds__(256) gemm_qkv_kernel(const uint4* __restrict__ Af,
                                                       const uint2* __restrict__ Bf,
                                                       const float* __restrict__ bias,
                                                       uint4* __restrict__ qf,
                                                       uint2* __restrict__ kf,
                                                       uint2* __restrict__ vf) {
    extern __shared__ char dynsm[];
    const uint32_t sb = smem_u32(dynsm);
    float* T = (float*)dynsm;
    const int tid = threadIdx.x, w = tid >> 5, l = tid & 31;
    const int mi = w >> 1, nh = w & 1, gid = l >> 2, tig = l & 3;
    const int nb = blockIdx.x, mb = blockIdx.y, bz = blockIdx.z;
    Bf += (size_t)bz * 524288;

    auto issue = [&](int kc, int s) {
        #pragma unroll
        for (int j = 0; j < 2; j++) {          // A: 512 x 16B
            const int e = tid + j * 256;
            const int bl = e >> 5, ln = e & 31;
            const int i = bl >> 1, ktl = bl & 1;
            cp16(sb + s * 16384 + e * 16,
                 (const char*)(Af + ((size_t)(mb * 8 + i) * 32 + kc * 2 + ktl) * 32 + ln));
        }
        #pragma unroll
        for (int j = 0; j < 2; j++) {          // B: 512 x 16B
            const int f = tid + j * 256;
            const int bl = f >> 4, lp = f & 15;
            const int nt = bl >> 1, ktl = bl & 1;
            cp16(sb + s * 16384 + 8192 + bl * 256 + lp * 16,
                 (const char*)Bf + ((size_t)(nb * 16 + nt) * 32 + kc * 2 + ktl) * 256 + lp * 16);
        }
    };

    issue(0, 0); CP_COMMIT();
    float acc[2][8][4] = {};
    for (int t = 0; t < 16; t++) {
        if (t + 1 < 16) { issue(t + 1, (t + 1) & 1); CP_COMMIT(); CP_WAIT(1); }
        else            { CP_WAIT(0); }
        __syncthreads();
        const int s = t & 1;
        #pragma unroll
        for (int ktl = 0; ktl < 2; ktl++) {
            uint4 A0 = *(const uint4*)(dynsm + s * 16384 + (((mi * 2 + 0) * 2 + ktl) * 32 + l) * 16);
            uint4 A1 = *(const uint4*)(dynsm + s * 16384 + (((mi * 2 + 1) * 2 + ktl) * 32 + l) * 16);
            #pragma unroll
            for (int nt = 0; nt < 8; nt++) {
                uint2 B = *(const uint2*)(dynsm + s * 16384 + 8192 + (((nh * 8 + nt) * 2 + ktl) * 32 + l) * 8);
                MMA_BF16(acc[0][nt], A0, B);
                MMA_BF16(acc[1][nt], A1, B);
            }
        }
        __syncthreads();   // buf s free; also guards epilogue's T overwrite of staging
    }

    const int sec = mb >> 2, h = mb & 3;
    const int bh = bz * NH + h;
    const float qs = (sec == 0) ? 0.08838834764831845f : 1.0f;  // 1/sqrt(128)

    // stage acc (+bias, x qs) into T[m][n], stride 130
    #pragma unroll
    for (int r = 0; r < 2; r++) {
        const int m0 = mi * 32 + r * 16 + gid;
        const float b0v = bias[mb * 128 + m0], b8v = bias[mb * 128 + m0 + 8];
        #pragma unroll
        for (int nt = 0; nt < 8; nt++) {
            const int n0 = nh * 64 + nt * 8 + 2 * tig;
            T[m0 * 130 + n0]           = (acc[r][nt][0] + b0v) * qs;
            T[m0 * 130 + n0 + 1]       = (acc[r][nt][1] + b0v) * qs;
            T[(m0 + 8) * 130 + n0]     = (acc[r][nt][2] + b8v) * qs;
            T[(m0 + 8) * 130 + n0 + 1] = (acc[r][nt][3] + b8v) * qs;
        }
    }
    __syncthreads();

    if (sec == 0) {
        // Q A-frags: qf[(bh*32 + nb)*2048 + idx]
        uint4* dst = qf + ((size_t)bh * 32 + nb) * 2048;
        #pragma unroll
        for (int it = 0; it < 8; it++) {
            const int idx = tid + it * 256;
            const int blk = idx >> 5, ln = idx & 31;
            const int mtb = blk >> 3, ktc = blk & 7;
            const int g2 = ln >> 2, t2 = ln & 3;
            const int q = mtb * 16 + g2, c = ktc * 16 + 2 * t2;
            uint4 o;
            o.x = pack_bf16x2(T[c * 130 + q],           T[(c + 1) * 130 + q]);
            o.y = pack_bf16x2(T[c * 130 + q + 8],       T[(c + 1) * 130 + q + 8]);
            o.z = pack_bf16x2(T[(c + 8) * 130 + q],     T[(c + 9) * 130 + q]);
            o.w = pack_bf16x2(T[(c + 8) * 130 + q + 8], T[(c + 9) * 130 + q + 8]);
            dst[idx] = o;
        }
    } else if (sec == 1) {
        // K B-frags: kf[bh*131072 + nb*4096 + idx]
        uint2* dst = kf + (size_t)bh * 131072 + (size_t)nb * 4096;
        #pragma unroll
        for (int it = 0; it < 16; it++) {
            const int idx = tid + it * 256;
            const int blk = idx >> 5, ln = idx & 31;
            const int ktc = blk >> 4, ntb = blk & 15;
            const int g2 = ln >> 2, t2 = ln & 3;
            const int key = ntb * 8 + g2, c0 = ktc * 16 + 2 * t2;
            uint2 o;
            o.x = pack_bf16x2(T[c0 * 130 + key],       T[(c0 + 1) * 130 + key]);
            o.y = pack_bf16x2(T[(c0 + 8) * 130 + key], T[(c0 + 9) * 130 + key]);
            dst[idx] = o;
        }
    } else {
        // V B-frags: vf[bh*131072 + nb*4096 + idx]
        uint2* dst = vf + (size_t)bh * 131072 + (size_t)nb * 4096;
        #pragma unroll
        for (int it = 0; it < 16; it++) {
            const int idx = tid + it * 256;
            const int blk = idx >> 5, ln = idx & 31;
            const int ktk = blk >> 4, ntb = blk & 15;
            const int g2 = ln >> 2, t2 = ln & 3;
            const int hd = ntb * 8 + g2, key0 = ktk * 16 + 2 * t2;
            uint2 o;
            o.x = pack_bf16x2(T[hd * 130 + key0],     T[hd * 130 + key0 + 1]);
            o.y = pack_bf16x2(T[hd * 130 + key0 + 8], T[hd * 130 + key0 + 9]);
            dst[idx] = o;
        }
    }
}

// ---------------- proj GEMM (bf16 mma, fp32 out + bias + residual) ----------------
__global__ void __launch_bounds__(256) gemm_bf16_kernel(const uint4* __restrict__ Af,
                                                        const uint2* __restrict__ Bf,
                                                        const float* __restrict__ bias,
                                                        const float* __restrict__ resid,
                                                        float* __restrict__ out, int M) {
    __shared__ char smbuf[32768];
    const uint32_t sb = smem_u32(smbuf);
    const int tid = threadIdx.x, w = tid >> 5, l = tid & 31;
    const int mi = w >> 1, nh = w & 1, gid = l >> 2, tig = l & 3;
    const int nb = blockIdx.x, mb = blockIdx.y, bz = blockIdx.z;
    Bf += (size_t)bz * 524288;
    out += (size_t)bz * M * L;
    if (resid) resid += (size_t)bz * M * L;

    auto issue = [&](int kc, int s) {
        #pragma unroll
        for (int j = 0; j < 2; j++) {
            const int e = tid + j * 256;
            const int bl = e >> 5, ln = e & 31;
            const int i = bl >> 1, ktl = bl & 1;
            cp16(sb + s * 16384 + e * 16,
                 (const char*)(Af + ((size_t)(mb * 8 + i) * 32 + kc * 2 + ktl) * 32 + ln));
        }
        #pragma unroll
        for (int j = 0; j < 2; j++) {
            const int f = tid + j * 256;
            const int bl = f >> 4, lp = f & 15;
            const int nt = bl >> 1, ktl = bl & 1;
            cp16(sb + s * 16384 + 8192 + bl * 256 + lp * 16,
                 (const char*)Bf + ((size_t)(nb * 16 + nt) * 32 + kc * 2 + ktl) * 256 + lp * 16);
        }
    };

    issue(0, 0); CP_COMMIT();
    float acc[2][8][4] = {};
    for (int t = 0; t < 16; t++) {
        if (t + 1 < 16) { issue(t + 1, (t + 1) & 1); CP_COMMIT(); CP_WAIT(1); }
        else            { CP_WAIT(0); }
        __syncthreads();
        const int s = t & 1;
        #pragma unroll
        for (int ktl = 0; ktl < 2; ktl++) {
            uint4 A0 = *(const uint4*)(smbuf + s * 16384 + (((mi * 2 + 0) * 2 + ktl) * 32 + l) * 16);
            uint4 A1 = *(const uint4*)(smbuf + s * 16384 + (((mi * 2 + 1) * 2 + ktl) * 32 + l) * 16);
            #pragma unroll
            for (int nt = 0; nt < 8; nt++) {
                uint2 B = *(const uint2*)(smbuf + s * 16384 + 8192 + (((nh * 8 + nt) * 2 + ktl) * 32 + l) * 8);
                MMA_BF16(acc[0][nt], A0, B);
                MMA_BF16(acc[1][nt], A1, B);
            }
        }
        __syncthreads();
    }

    #pragma unroll
    for (int r = 0; r < 2; r++) {
        const int m0 = mb * 128 + mi * 32 + r * 16 + gid;
        const float b0v = bias[m0], b8v = bias[m0 + 8];
        #pragma unroll
        for (int nt = 0; nt < 8; nt++) {
            const int n0 = nb * 128 + nh * 64 + nt * 8 + 2 * tig;
            const size_t o0 = (size_t)m0 * L + n0, o8 = (size_t)(m0 + 8) * L + n0;
            float2 v0 = make_float2(acc[r][nt][0] + b0v, acc[r][nt][1] + b0v);
            float2 v8 = make_float2(acc[r][nt][2] + b8v, acc[r][nt][3] + b8v);
            if (resid) {
                float2 r0 = *(const float2*)(resid + o0);
                float2 r8 = *(const float2*)(resid + o8);
                v0.x += r0.x; v0.y += r0.y; v8.x += r8.x; v8.y += r8.y;
            }
            *(float2*)(out + o0) = v0;
            *(float2*)(out + o8) = v8;
        }
    }
}

// ---------------- bf16 mma flash attention, cp.async double-buffered ----------------
#define SM_Q  0
#define SM_K0 32768
#define SM_V0 98304
#define SM_P  163840
#define ATT_SMEM 196608

__global__ void __launch_bounds__(256) attn_bf16_kernel(const uint4* __restrict__ qf,
                                                        const uint2* __restrict__ kf,
                                                        const uint2* __restrict__ vf,
                                                        uint2* __restrict__ attf) {
    extern __shared__ char sm[];
    const uint32_t sb = smem_u32(sm);
    __shared__ float lsum_s[2][128];

    const int tid = threadIdx.x, w = tid >> 5, l = tid & 31;
    const int qi = w >> 1, kh = w & 1;
    const int gid = l >> 2, tig = l & 3;
    const int qb = blockIdx.x, bh = blockIdx.y;
    const int b = bh >> 2, h = bh & 3;

    const char* qsrc = (const char*)(qf + ((size_t)bh * 32 + qb) * 2048);
    const char* ksrc = (const char*)(kf + (size_t)bh * 131072);
    const char* vsrc = (const char*)(vf + (size_t)bh * 131072);

    #pragma unroll
    for (int j = 0; j < 8; j++) {
        const int i = tid + j * 256;
        cp16(sb + SM_Q + i * 16, qsrc + i * 16);
        cp16(sb + SM_K0 + i * 16, ksrc + i * 16);
        cp16(sb + SM_V0 + i * 16, vsrc + i * 16);
    }
    CP_COMMIT();

    float oacc[2][8][4] = {};
    float lsum[2][2] = {};

    for (int t = 0; t < 32; t++) {
        __syncthreads();
        if (t + 1 < 32) {
            const int pb = (t + 1) & 1;
            const char* kp = ksrc + (size_t)(t + 1) * 32768;
            const char* vp = vsrc + (size_t)(t + 1) * 32768;
            #pragma unroll
            for (int j = 0; j < 8; j++) {
                const int i = tid + j * 256;
                cp16(sb + SM_K0 + pb * 32768 + i * 16, kp + i * 16);
                cp16(sb + SM_V0 + pb * 32768 + i * 16, vp + i * 16);
            }
            CP_COMMIT();
            CP_WAIT(1);
        } else {
            CP_WAIT(0);
        }
        __syncthreads();

        const uint32_t Kb = SM_K0 + (t & 1) * 32768;
        float sacc[2][8][4] = {};
        #pragma unroll
        for (int ktc = 0; ktc < 8; ktc++) {
            uint4 A0 = *(const uint4*)(sm + SM_Q + (((qi * 2 + 0) * 8 + ktc) * 32 + l) * 16);
            uint4 A1 = *(const uint4*)(sm + SM_Q + (((qi * 2 + 1) * 8 + ktc) * 32 + l) * 16);
            #pragma unroll
            for (int nt = 0; nt < 8; nt++) {
                uint2 B = *(const uint2*)(sm + Kb + ((ktc * 16 + kh * 8 + nt) * 32 + l) * 8);
                MMA_BF16(sacc[0][nt], A0, B);
                MMA_BF16(sacc[1][nt], A1, B);
            }
        }

        #pragma unroll
        for (int mt = 0; mt < 2; mt++) {
            #pragma unroll
            for (int kc = 0; kc < 4; kc++) {
                const int nt0 = 2 * kc, nt1 = 2 * kc + 1;
                float p00 = __expf(sacc[mt][nt0][0]), p01 = __expf(sacc[mt][nt0][1]);
                float p02 = __expf(sacc[mt][nt0][2]), p03 = __expf(sacc[mt][nt0][3]);
                float p10 = __expf(sacc[mt][nt1][0]), p11 = __expf(sacc[mt][nt1][1]);
                float p12 = __expf(sacc[mt][nt1][2]), p13 = __expf(sacc[mt][nt1][3]);
                lsum[mt][0] += p00 + p01 + p10 + p11;
                lsum[mt][1] += p02 + p03 + p12 + p13;
                uint4 o;
                o.x = pack_bf16x2(p00, p01);
                o.y = pack_bf16x2(p02, p03);
                o.z = pack_bf16x2(p10, p11);
                o.w = pack_bf16x2(p12, p13);
                *(uint4*)(sm + SM_P + (((qi * 2 + mt) * 8 + (kh * 4 + kc)) * 32 + l) * 16) = o;
            }
        }
        __syncthreads();

        const uint32_t Vb = SM_V0 + (t & 1) * 32768;
        #pragma unroll
        for (int kt = 0; kt < 8; kt++) {
            uint4 A0 = *(const uint4*)(sm + SM_P + (((qi * 2 + 0) * 8 + kt) * 32 + l) * 16);
            uint4 A1 = *(const uint4*)(sm + SM_P + (((qi * 2 + 1) * 8 + kt) * 32 + l) * 16);
            #pragma unroll
            for (int nt = 0; nt < 8; nt++) {
                uint2 B = *(const uint2*)(sm + Vb + ((kt * 16 + kh * 8 + nt) * 32 + l) * 8);
                MMA_BF16(oacc[0][nt], A0, B);
                MMA_BF16(oacc[1][nt], A1, B);
            }
        }
    }

    #pragma unroll
    for (int mt = 0; mt < 2; mt++)
        #pragma unroll
        for (int dr = 0; dr < 2; dr++) {
            float v = lsum[mt][dr];
            v += __shfl_xor_sync(0xffffffffu, v, 1);
            v += __shfl_xor_sync(0xffffffffu, v, 2);
            lsum[mt][dr] = v;
        }
    __syncthreads();
    if (tig == 0) {
        #pragma unroll
        for (int mt = 0; mt < 2; mt++)
            #pragma unroll
            for (int dr = 0; dr < 2; dr++)
                lsum_s[kh][qi * 32 + mt * 16 + gid + 8 * dr] = lsum[mt][dr];
    }
    __syncthreads();

    float* Ob = (float*)sm;
    #pragma unroll
    for (int mt = 0; mt < 2; mt++) {
        const int r0 = qi * 32 + mt * 16 + gid;
        const float linv0 = 1.0f / (lsum_s[0][r0] + lsum_s[1][r0]);
        const float linv1 = 1.0f / (lsum_s[0][r0 + 8] + lsum_s[1][r0 + 8]);
        #pragma unroll
        for (int nt = 0; nt < 8; nt++) {
            #pragma unroll
            for (int j = 0; j < 4; j++) {
                const int q  = r0 + 8 * (j >> 1);
                const int hd = kh * 64 + nt * 8 + tig * 2 + (j & 1);
                Ob[hd * 132 + q] = oacc[mt][nt][j] * ((j >> 1) ? linv1 : linv0);
            }
        }
    }
    __syncthreads();

    const size_t attbase = (size_t)b * 524288;
    #pragma unroll
    for (int it = 0; it < 16; it++) {
        const int slot = tid + it * 256;
        const int lb = slot >> 5, ln = slot & 31;
        const int ntl = lb >> 3, ktl = lb & 7;
        const int g2 = ln >> 2, t2 = ln & 3;
        const int cl = ktl * 16 + 2 * t2;
        const int ql = ntl * 8 + g2;
        uint2 o;
        o.x = pack_bf16x2(Ob[cl * 132 + ql],       Ob[(cl + 1) * 132 + ql]);
        o.y = pack_bf16x2(Ob[(cl + 8) * 132 + ql], Ob[(cl + 9) * 132 + ql]);
        attf[attbase + ((size_t)(qb * 16 + ntl) * 32 + (h * 8 + ktl)) * 32 + ln] = o;
    }
}

// ---------------- host ----------------
extern "C" void kernel_launch(void* const* d_in, const int* in_sizes, int n_in,
                              void* d_out, int out_size) {
    const float* x      = (const float*)d_in[0];
    const float* gn_w   = (const float*)d_in[1];
    const float* gn_b   = (const float*)d_in[2];
    const float* w_qkv  = (const float*)d_in[3];
    const float* b_qkv  = (const float*)d_in[4];
    const float* w_proj = (const float*)d_in[5];
    const float* b_proj = (const float*)d_in[6];
    float* out = (float*)d_out;

    uint4 *qf_p, *wqf_p, *wpf_p;
    uint2 *kf_p, *vf_p, *xnf_p, *attf_p;
    cudaGetSymbolAddress((void**)&qf_p, g_qf);
    cudaGetSymbolAddress((void**)&kf_p, g_kf);
    cudaGetSymbolAddress((void**)&vf_p, g_vf);
    cudaGetSymbolAddress((void**)&xnf_p, g_xnf);
    cudaGetSymbolAddress((void**)&attf_p, g_attf);
    cudaGetSymbolAddress((void**)&wqf_p, g_wqf);
    cudaGetSymbolAddress((void**)&wpf_p, g_wpf);

    // 1) GroupNorm fused with xn fragment packing; weight packing
    groupnorm_pack_kernel<<<dim3(GROUPS, BATCH), 256>>>(x, gn_w, gn_b, xnf_p);
    pack_w_kernel<<<384, 256>>>(w_qkv, wqf_p);
    pack_w_kernel<<<128, 256>>>(w_proj, wpf_p);

    // 2) QKV GEMM with fused q/k/v fragment epilogue
    cudaFuncSetAttribute(gemm_qkv_kernel, cudaFuncAttributeMaxDynamicSharedMemorySize, QKV_SMEM);
    gemm_qkv_kernel<<<dim3(32, 12, BATCH), 256, QKV_SMEM>>>(wqf_p, xnf_p, b_qkv,
                                                            qf_p, kf_p, vf_p);

    // 3) attention (bf16 mma), emits proj B-frags
    cudaFuncSetAttribute(attn_bf16_kernel, cudaFuncAttributeMaxDynamicSharedMemorySize, ATT_SMEM);
    attn_bf16_kernel<<<dim3(L / 128, BATCH * NH), 256, ATT_SMEM>>>(qf_p, kf_p, vf_p, attf_p);

    // 4) proj GEMM + bias + residual -> out
    gemm_bf16_kernel<<<dim3(32, 4, BATCH), 256>>>(wpf_p, attf_p, b_proj, x, out, C);
}

// round 7
// speedup vs baseline: 9.5470x; 1.0590x over previous
#include <cuda_runtime.h>
#include <math.h>
#include <stdint.h>

#define BATCH 2
#define C 512
#define L 4096
#define NH 4
#define HD 128
#define GROUPS 32
#define CPG (C / GROUPS)   // 16
#define EPS 1e-5f

// ---------------- scratch (static device globals; no allocation) ----------------
__device__ uint4 g_qf[(size_t)BATCH * NH * 32 * 2048];   // 8 MB  Q A-frags
__device__ uint2 g_kf[(size_t)BATCH * NH * 32 * 4096];   // 8 MB  K B-frags
__device__ uint2 g_vf[(size_t)BATCH * NH * 32 * 4096];   // 8 MB  V B-frags
__device__ uint2 g_xnf[(size_t)BATCH * 512 * 32 * 32];   // 8 MB  xn B-frags
__device__ uint2 g_attf[(size_t)BATCH * 512 * 32 * 32];  // 8 MB  att B-frags
__device__ uint4 g_wqf[(size_t)96 * 32 * 32];            // 1.5MB w_qkv A-frags
__device__ uint4 g_wpf[(size_t)32 * 32 * 32];            // 0.5MB w_proj A-frags

__device__ __forceinline__ uint32_t smem_u32(const void* p) {
    uint32_t a;
    asm("{ .reg .u64 t; cvta.to.shared.u64 t, %1; cvt.u32.u64 %0, t; }" : "=r"(a) : "l"(p));
    return a;
}
__device__ __forceinline__ uint32_t pack_bf16x2(float lo, float hi) {
    uint32_t d;
    asm("cvt.rn.bf16x2.f32 %0, %1, %2;" : "=r"(d) : "f"(hi), "f"(lo));
    return d;
}
#define MMA_BF16(d, a, b) \
    asm volatile("mma.sync.aligned.m16n8k16.row.col.f32.bf16.bf16.f32 " \
                 "{%0,%1,%2,%3}, {%4,%5,%6,%7}, {%8,%9}, {%0,%1,%2,%3};" \
                 : "+f"((d)[0]), "+f"((d)[1]), "+f"((d)[2]), "+f"((d)[3]) \
                 : "r"((a).x), "r"((a).y), "r"((a).z), "r"((a).w), \
                   "r"((b).x), "r"((b).y))

__device__ __forceinline__ void cp16(uint32_t dst, const void* src) {
    asm volatile("cp.async.cg.shared.global [%0], [%1], 16;" :: "r"(dst), "l"(src));
}
#define CP_COMMIT() asm volatile("cp.async.commit_group;" ::: "memory")
#define CP_WAIT(n)  asm volatile("cp.async.wait_group %0;" :: "n"(n) : "memory")

// ---------------- GroupNorm fused with xn fragment packing ----------------
__global__ void __launch_bounds__(256) groupnorm_pack_kernel(const float* __restrict__ x,
                                                             const float* __restrict__ gw,
                                                             const float* __restrict__ gb,
                                                             uint2* __restrict__ Bf) {
    const int g = blockIdx.x, b = blockIdx.y;
    const int tid = threadIdx.x;
    const size_t base = ((size_t)b * C + g * CPG) * L;
    const int SPAN = CPG * L;
    const float* xr = x + base;
    const float4* x4 = (const float4*)xr;
    float s = 0.f, ss = 0.f;
    for (int i = tid; i < SPAN / 4; i += 256) {
        float4 v = x4[i];
        s  += v.x + v.y + v.z + v.w;
        ss += v.x * v.x + v.y * v.y + v.z * v.z + v.w * v.w;
    }
    __shared__ float rs[256], rss[256];
    rs[tid] = s; rss[tid] = ss;
    __syncthreads();
    for (int off = 128; off; off >>= 1) {
        if (tid < off) { rs[tid] += rs[tid + off]; rss[tid] += rss[tid + off]; }
        __syncthreads();
    }
    __shared__ float ga_s[CPG], be_s[CPG];
    if (tid < CPG) {
        float mean = rs[0] / SPAN;
        float var  = rss[0] / SPAN - mean * mean;
        float rstd = rsqrtf(var + EPS);
        float ga = gw[g * CPG + tid] * rstd;
        ga_s[tid] = ga;
        be_s[tid] = gb[g * CPG + tid] - mean * ga;
    }
    __syncthreads();

    uint2* dst = Bf + (size_t)b * 524288 + (size_t)g * 32;
    for (int i = tid; i < 16384; i += 256) {
        const int nt = i >> 5, lane = i & 31;
        const int gid = lane >> 2, tig = lane & 3;
        const int n = nt * 8 + gid;
        const int lc = 2 * tig;
        float v0 = xr[(size_t)lc * L + n]       * ga_s[lc]     + be_s[lc];
        float v1 = xr[(size_t)(lc + 1) * L + n] * ga_s[lc + 1] + be_s[lc + 1];
        float v8 = xr[(size_t)(lc + 8) * L + n] * ga_s[lc + 8] + be_s[lc + 8];
        float v9 = xr[(size_t)(lc + 9) * L + n] * ga_s[lc + 9] + be_s[lc + 9];
        uint2 o;
        o.x = pack_bf16x2(v0, v1);
        o.y = pack_bf16x2(v8, v9);
        dst[(size_t)nt * 1024 + lane] = o;
    }
}

// ---------------- weight packing ----------------
__global__ void __launch_bounds__(256) pack_w_kernel(const float* __restrict__ W,
                                                     uint4* __restrict__ Wf) {
    const int idx = blockIdx.x * 256 + threadIdx.x;
    const int blk = idx >> 5, lane = idx & 31;
    const int mt = blk >> 5, kt = blk & 31;
    const int gid = lane >> 2, tig = lane & 3;
    const float* r0 = W + (size_t)(mt * 16 + gid) * 512 + kt * 16;
    const float* r8 = r0 + 8 * 512;
    float2 a0 = *(const float2*)(r0 + 2 * tig);
    float2 a1 = *(const float2*)(r8 + 2 * tig);
    float2 a2 = *(const float2*)(r0 + 2 * tig + 8);
    float2 a3 = *(const float2*)(r8 + 2 * tig + 8);
    uint4 o;
    o.x = pack_bf16x2(a0.x, a0.y); o.y = pack_bf16x2(a1.x, a1.y);
    o.z = pack_bf16x2(a2.x, a2.y); o.w = pack_bf16x2(a3.x, a3.y);
    Wf[idx] = o;
}

// ---------------- QKV GEMM with fused q/k/v fragment epilogue ----------------
#define QKV_SMEM 66560

__global__ void __launch_bounds__(256) gemm_qkv_kernel(const uint4* __restrict__ Af,
                                                       const uint2* __restrict__ Bf,
                                                       const float* __restrict__ bias,
                                                       uint4* __restrict__ qf,
                                                       uint2* __restrict__ kf,
                                                       uint2* __restrict__ vf) {
    extern __shared__ char dynsm[];
    const uint32_t sb = smem_u32(dynsm);
    float* T = (float*)dynsm;
    const int tid = threadIdx.x, w = tid >> 5, l = tid & 31;
    const int mi = w >> 1, nh = w & 1, gid = l >> 2, tig = l & 3;
    const int nb = blockIdx.x, mb = blockIdx.y, bz = blockIdx.z;
    Bf += (size_t)bz * 524288;

    auto issue = [&](int kc, int s) {
        #pragma unroll
        for (int j = 0; j < 2; j++) {
            const int e = tid + j * 256;
            const int bl = e >> 5, ln = e & 31;
            const int i = bl >> 1, ktl = bl & 1;
            cp16(sb + s * 16384 + e * 16,
                 (const char*)(Af + ((size_t)(mb * 8 + i) * 32 + kc * 2 + ktl) * 32 + ln));
        }
        #pragma unroll
        for (int j = 0; j < 2; j++) {
            const int f = tid + j * 256;
            const int bl = f >> 4, lp = f & 15;
            const int nt = bl >> 1, ktl = bl & 1;
            cp16(sb + s * 16384 + 8192 + bl * 256 + lp * 16,
                 (const char*)Bf + ((size_t)(nb * 16 + nt) * 32 + kc * 2 + ktl) * 256 + lp * 16);
        }
    };

    issue(0, 0); CP_COMMIT();
    float acc[2][8][4] = {};
    for (int t = 0; t < 16; t++) {
        CP_WAIT(0);
        __syncthreads();
        if (t + 1 < 16) { issue(t + 1, (t + 1) & 1); CP_COMMIT(); }
        const int s = t & 1;
        #pragma unroll
        for (int ktl = 0; ktl < 2; ktl++) {
            uint4 A0 = *(const uint4*)(dynsm + s * 16384 + (((mi * 2 + 0) * 2 + ktl) * 32 + l) * 16);
            uint4 A1 = *(const uint4*)(dynsm + s * 16384 + (((mi * 2 + 1) * 2 + ktl) * 32 + l) * 16);
            #pragma unroll
            for (int nt = 0; nt < 8; nt++) {
                uint2 B = *(const uint2*)(dynsm + s * 16384 + 8192 + (((nh * 8 + nt) * 2 + ktl) * 32 + l) * 8);
                MMA_BF16(acc[0][nt], A0, B);
                MMA_BF16(acc[1][nt], A1, B);
            }
        }
    }
    __syncthreads();   // all warps done with staging before T overwrites it

    const int sec = mb >> 2, h = mb & 3;
    const int bh = bz * NH + h;
    const float qs = (sec == 0) ? 0.08838834764831845f : 1.0f;

    #pragma unroll
    for (int r = 0; r < 2; r++) {
        const int m0 = mi * 32 + r * 16 + gid;
        const float b0v = bias[mb * 128 + m0], b8v = bias[mb * 128 + m0 + 8];
        #pragma unroll
        for (int nt = 0; nt < 8; nt++) {
            const int n0 = nh * 64 + nt * 8 + 2 * tig;
            T[m0 * 130 + n0]           = (acc[r][nt][0] + b0v) * qs;
            T[m0 * 130 + n0 + 1]       = (acc[r][nt][1] + b0v) * qs;
            T[(m0 + 8) * 130 + n0]     = (acc[r][nt][2] + b8v) * qs;
            T[(m0 + 8) * 130 + n0 + 1] = (acc[r][nt][3] + b8v) * qs;
        }
    }
    __syncthreads();

    if (sec == 0) {
        uint4* dst = qf + ((size_t)bh * 32 + nb) * 2048;
        #pragma unroll
        for (int it = 0; it < 8; it++) {
            const int idx = tid + it * 256;
            const int blk = idx >> 5, ln = idx & 31;
            const int mtb = blk >> 3, ktc = blk & 7;
            const int g2 = ln >> 2, t2 = ln & 3;
            const int q = mtb * 16 + g2, c = ktc * 16 + 2 * t2;
            uint4 o;
            o.x = pack_bf16x2(T[c * 130 + q],           T[(c + 1) * 130 + q]);
            o.y = pack_bf16x2(T[c * 130 + q + 8],       T[(c + 1) * 130 + q + 8]);
            o.z = pack_bf16x2(T[(c + 8) * 130 + q],     T[(c + 9) * 130 + q]);
            o.w = pack_bf16x2(T[(c + 8) * 130 + q + 8], T[(c + 9) * 130 + q + 8]);
            dst[idx] = o;
        }
    } else if (sec == 1) {
        uint2* dst = kf + (size_t)bh * 131072 + (size_t)nb * 4096;
        #pragma unroll
        for (int it = 0; it < 16; it++) {
            const int idx = tid + it * 256;
            const int blk = idx >> 5, ln = idx & 31;
            const int ktc = blk >> 4, ntb = blk & 15;
            const int g2 = ln >> 2, t2 = ln & 3;
            const int key = ntb * 8 + g2, c0 = ktc * 16 + 2 * t2;
            uint2 o;
            o.x = pack_bf16x2(T[c0 * 130 + key],       T[(c0 + 1) * 130 + key]);
            o.y = pack_bf16x2(T[(c0 + 8) * 130 + key], T[(c0 + 9) * 130 + key]);
            dst[idx] = o;
        }
    } else {
        uint2* dst = vf + (size_t)bh * 131072 + (size_t)nb * 4096;
        #pragma unroll
        for (int it = 0; it < 16; it++) {
            const int idx = tid + it * 256;
            const int blk = idx >> 5, ln = idx & 31;
            const int ktk = blk >> 4, ntb = blk & 15;
            const int g2 = ln >> 2, t2 = ln & 3;
            const int hd = ntb * 8 + g2, key0 = ktk * 16 + 2 * t2;
            uint2 o;
            o.x = pack_bf16x2(T[hd * 130 + key0],     T[hd * 130 + key0 + 1]);
            o.y = pack_bf16x2(T[hd * 130 + key0 + 8], T[hd * 130 + key0 + 9]);
            dst[idx] = o;
        }
    }
}

// ---------------- proj GEMM (bf16 mma, fp32 out + bias + residual) ----------------
__global__ void __launch_bounds__(256) gemm_bf16_kernel(const uint4* __restrict__ Af,
                                                        const uint2* __restrict__ Bf,
                                                        const float* __restrict__ bias,
                                                        const float* __restrict__ resid,
                                                        float* __restrict__ out, int M) {
    __shared__ char smbuf[32768];
    const uint32_t sb = smem_u32(smbuf);
    const int tid = threadIdx.x, w = tid >> 5, l = tid & 31;
    const int mi = w >> 1, nh = w & 1, gid = l >> 2, tig = l & 3;
    const int nb = blockIdx.x, mb = blockIdx.y, bz = blockIdx.z;
    Bf += (size_t)bz * 524288;
    out += (size_t)bz * M * L;
    if (resid) resid += (size_t)bz * M * L;

    auto issue = [&](int kc, int s) {
        #pragma unroll
        for (int j = 0; j < 2; j++) {
            const int e = tid + j * 256;
            const int bl = e >> 5, ln = e & 31;
            const int i = bl >> 1, ktl = bl & 1;
            cp16(sb + s * 16384 + e * 16,
                 (const char*)(Af + ((size_t)(mb * 8 + i) * 32 + kc * 2 + ktl) * 32 + ln));
        }
        #pragma unroll
        for (int j = 0; j < 2; j++) {
            const int f = tid + j * 256;
            const int bl = f >> 4, lp = f & 15;
            const int nt = bl >> 1, ktl = bl & 1;
            cp16(sb + s * 16384 + 8192 + bl * 256 + lp * 16,
                 (const char*)Bf + ((size_t)(nb * 16 + nt) * 32 + kc * 2 + ktl) * 256 + lp * 16);
        }
    };

    issue(0, 0); CP_COMMIT();
    float acc[2][8][4] = {};
    for (int t = 0; t < 16; t++) {
        CP_WAIT(0);
        __syncthreads();
        if (t + 1 < 16) { issue(t + 1, (t + 1) & 1); CP_COMMIT(); }
        const int s = t & 1;
        #pragma unroll
        for (int ktl = 0; ktl < 2; ktl++) {
            uint4 A0 = *(const uint4*)(smbuf + s * 16384 + (((mi * 2 + 0) * 2 + ktl) * 32 + l) * 16);
            uint4 A1 = *(const uint4*)(smbuf + s * 16384 + (((mi * 2 + 1) * 2 + ktl) * 32 + l) * 16);
            #pragma unroll
            for (int nt = 0; nt < 8; nt++) {
                uint2 B = *(const uint2*)(smbuf + s * 16384 + 8192 + (((nh * 8 + nt) * 2 + ktl) * 32 + l) * 8);
                MMA_BF16(acc[0][nt], A0, B);
                MMA_BF16(acc[1][nt], A1, B);
            }
        }
    }

    #pragma unroll
    for (int r = 0; r < 2; r++) {
        const int m0 = mb * 128 + mi * 32 + r * 16 + gid;
        const float b0v = bias[m0], b8v = bias[m0 + 8];
        #pragma unroll
        for (int nt = 0; nt < 8; nt++) {
            const int n0 = nb * 128 + nh * 64 + nt * 8 + 2 * tig;
            const size_t o0 = (size_t)m0 * L + n0, o8 = (size_t)(m0 + 8) * L + n0;
            float2 v0 = make_float2(acc[r][nt][0] + b0v, acc[r][nt][1] + b0v);
            float2 v8 = make_float2(acc[r][nt][2] + b8v, acc[r][nt][3] + b8v);
            if (resid) {
                float2 r0 = *(const float2*)(resid + o0);
                float2 r8 = *(const float2*)(resid + o8);
                v0.x += r0.x; v0.y += r0.y; v8.x += r8.x; v8.y += r8.y;
            }
            *(float2*)(out + o0) = v0;
            *(float2*)(out + o8) = v8;
        }
    }
}

// ---------------- bf16 mma flash attention: register-resident P ----------------
// Warp (qi, kh): 32 queries, key half kh (64 keys) -> partial O over full 128 hd.
// smem: Q 32K | K0 32K | K1 32K | V0 32K | V1 32K = 160KB; Ob overlays Q+K0 at end.
#define SM_Q  0
#define SM_K0 32768
#define SM_V0 98304
#define ATT_SMEM 163840

__global__ void __launch_bounds__(256) attn_bf16_kernel(const uint4* __restrict__ qf,
                                                        const uint2* __restrict__ kf,
                                                        const uint2* __restrict__ vf,
                                                        uint2* __restrict__ attf) {
    extern __shared__ char sm[];
    const uint32_t sb = smem_u32(sm);
    __shared__ float lsum_s[2][128];

    const int tid = threadIdx.x, w = tid >> 5, l = tid & 31;
    const int qi = w >> 1, kh = w & 1;
    const int gid = l >> 2, tig = l & 3;
    const int qb = blockIdx.x, bh = blockIdx.y;
    const int b = bh >> 2, h = bh & 3;

    const char* qsrc = (const char*)(qf + ((size_t)bh * 32 + qb) * 2048);
    const char* ksrc = (const char*)(kf + (size_t)bh * 131072);
    const char* vsrc = (const char*)(vf + (size_t)bh * 131072);

    #pragma unroll
    for (int j = 0; j < 8; j++) {
        const int i = tid + j * 256;
        cp16(sb + SM_Q + i * 16, qsrc + i * 16);
        cp16(sb + SM_K0 + i * 16, ksrc + i * 16);
        cp16(sb + SM_V0 + i * 16, vsrc + i * 16);
    }
    CP_COMMIT();

    float oacc[2][16][4] = {};
    float lsum[2][2] = {};

    for (int t = 0; t < 32; t++) {
        CP_WAIT(0);
        __syncthreads();   // tile t visible; everyone done with buf (t+1)&1 from t-1
        if (t + 1 < 32) {
            const int pb = (t + 1) & 1;
            const char* kp = ksrc + (size_t)(t + 1) * 32768;
            const char* vp = vsrc + (size_t)(t + 1) * 32768;
            #pragma unroll
            for (int j = 0; j < 8; j++) {
                const int i = tid + j * 256;
                cp16(sb + SM_K0 + pb * 32768 + i * 16, kp + i * 16);
                cp16(sb + SM_V0 + pb * 32768 + i * 16, vp + i * 16);
            }
            CP_COMMIT();
        }

        const uint32_t Kb = SM_K0 + (t & 1) * 32768;
        // ---- S = Q K^T (warp: 32q x its 64-key half) ----
        float sacc[2][8][4] = {};
        #pragma unroll
        for (int ktc = 0; ktc < 8; ktc++) {
            uint4 A0 = *(const uint4*)(sm + SM_Q + (((qi * 2 + 0) * 8 + ktc) * 32 + l) * 16);
            uint4 A1 = *(const uint4*)(sm + SM_Q + (((qi * 2 + 1) * 8 + ktc) * 32 + l) * 16);
            #pragma unroll
            for (int nt = 0; nt < 8; nt++) {
                uint2 B = *(const uint2*)(sm + Kb + ((ktc * 16 + kh * 8 + nt) * 32 + l) * 8);
                MMA_BF16(sacc[0][nt], A0, B);
                MMA_BF16(sacc[1][nt], A1, B);
            }
        }

        // ---- exp + pack P into PV A-fragment registers (no smem) ----
        uint4 pP[2][4];
        #pragma unroll
        for (int mt = 0; mt < 2; mt++) {
            #pragma unroll
            for (int kc = 0; kc < 4; kc++) {
                const int nt0 = 2 * kc, nt1 = 2 * kc + 1;
                float p00 = __expf(sacc[mt][nt0][0]), p01 = __expf(sacc[mt][nt0][1]);
                float p02 = __expf(sacc[mt][nt0][2]), p03 = __expf(sacc[mt][nt0][3]);
                float p10 = __expf(sacc[mt][nt1][0]), p11 = __expf(sacc[mt][nt1][1]);
                float p12 = __expf(sacc[mt][nt1][2]), p13 = __expf(sacc[mt][nt1][3]);
                lsum[mt][0] += p00 + p01 + p10 + p11;
                lsum[mt][1] += p02 + p03 + p12 + p13;
                pP[mt][kc].x = pack_bf16x2(p00, p01);
                pP[mt][kc].y = pack_bf16x2(p02, p03);
                pP[mt][kc].z = pack_bf16x2(p10, p11);
                pP[mt][kc].w = pack_bf16x2(p12, p13);
            }
        }

        // ---- O += P V over this warp's 64 keys, all 128 hd ----
        const uint32_t Vb = SM_V0 + (t & 1) * 32768;
        #pragma unroll
        for (int kt = 0; kt < 4; kt++) {
            const uint4 A0 = pP[0][kt], A1 = pP[1][kt];
            #pragma unroll
            for (int nt = 0; nt < 16; nt++) {
                uint2 B = *(const uint2*)(sm + Vb + (((kh * 4 + kt) * 16 + nt) * 32 + l) * 8);
                MMA_BF16(oacc[0][nt], A0, B);
                MMA_BF16(oacc[1][nt], A1, B);
            }
        }
    }

    // ---- lsum quad-reduce, publish per key-half ----
    #pragma unroll
    for (int mt = 0; mt < 2; mt++)
        #pragma unroll
        for (int dr = 0; dr < 2; dr++) {
            float v = lsum[mt][dr];
            v += __shfl_xor_sync(0xffffffffu, v, 1);
            v += __shfl_xor_sync(0xffffffffu, v, 2);
            lsum[mt][dr] = v;
        }
    __syncthreads();   // all compute done; smem free for Ob
    float* Ob = (float*)sm;   // [128 hd][stride 132] fp32
    if (tig == 0) {
        #pragma unroll
        for (int mt = 0; mt < 2; mt++)
            #pragma unroll
            for (int dr = 0; dr < 2; dr++)
                lsum_s[kh][qi * 32 + mt * 16 + gid + 8 * dr] = lsum[mt][dr];
    }
    // key-half 0 writes its partial O
    if (kh == 0) {
        #pragma unroll
        for (int mt = 0; mt < 2; mt++)
            #pragma unroll
            for (int nt = 0; nt < 16; nt++)
                #pragma unroll
                for (int j = 0; j < 4; j++) {
                    const int q  = qi * 32 + mt * 16 + gid + 8 * (j >> 1);
                    const int hd = nt * 8 + tig * 2 + (j & 1);
                    Ob[hd * 132 + q] = oacc[mt][nt][j];
                }
    }
    __syncthreads();
    // key-half 1 accumulates
    if (kh == 1) {
        #pragma unroll
        for (int mt = 0; mt < 2; mt++)
            #pragma unroll
            for (int nt = 0; nt < 16; nt++)
                #pragma unroll
                for (int j = 0; j < 4; j++) {
                    const int q  = qi * 32 + mt * 16 + gid + 8 * (j >> 1);
                    const int hd = nt * 8 + tig * 2 + (j & 1);
                    Ob[hd * 132 + q] += oacc[mt][nt][j];
                }
    }
    __syncthreads();

    // ---- pack proj B-frags with normalization ----
    const size_t attbase = (size_t)b * 524288;
    #pragma unroll
    for (int it = 0; it < 16; it++) {
        const int slot = tid + it * 256;
        const int lb = slot >> 5, ln = slot & 31;
        const int ntl = lb >> 3, ktl = lb & 7;
        const int g2 = ln >> 2, t2 = ln & 3;
        const int cl = ktl * 16 + 2 * t2;
        const int ql = ntl * 8 + g2;
        const float linv = 1.0f / (lsum_s[0][ql] + lsum_s[1][ql]);
        uint2 o;
        o.x = pack_bf16x2(Ob[cl * 132 + ql] * linv,       Ob[(cl + 1) * 132 + ql] * linv);
        o.y = pack_bf16x2(Ob[(cl + 8) * 132 + ql] * linv, Ob[(cl + 9) * 132 + ql] * linv);
        attf[attbase + ((size_t)(qb * 16 + ntl) * 32 + (h * 8 + ktl)) * 32 + ln] = o;
    }
}

// ---------------- host ----------------
extern "C" void kernel_launch(void* const* d_in, const int* in_sizes, int n_in,
                              void* d_out, int out_size) {
    const float* x      = (const float*)d_in[0];
    const float* gn_w   = (const float*)d_in[1];
    const float* gn_b   = (const float*)d_in[2];
    const float* w_qkv  = (const float*)d_in[3];
    const float* b_qkv  = (const float*)d_in[4];
    const float* w_proj = (const float*)d_in[5];
    const float* b_proj = (const float*)d_in[6];
    float* out = (float*)d_out;

    uint4 *qf_p, *wqf_p, *wpf_p;
    uint2 *kf_p, *vf_p, *xnf_p, *attf_p;
    cudaGetSymbolAddress((void**)&qf_p, g_qf);
    cudaGetSymbolAddress((void**)&kf_p, g_kf);
    cudaGetSymbolAddress((void**)&vf_p, g_vf);
    cudaGetSymbolAddress((void**)&xnf_p, g_xnf);
    cudaGetSymbolAddress((void**)&attf_p, g_attf);
    cudaGetSymbolAddress((void**)&wqf_p, g_wqf);
    cudaGetSymbolAddress((void**)&wpf_p, g_wpf);

    // 1) GroupNorm fused with xn fragment packing; weight packing
    groupnorm_pack_kernel<<<dim3(GROUPS, BATCH), 256>>>(x, gn_w, gn_b, xnf_p);
    pack_w_kernel<<<384, 256>>>(w_qkv, wqf_p);
    pack_w_kernel<<<128, 256>>>(w_proj, wpf_p);

    // 2) QKV GEMM with fused q/k/v fragment epilogue
    cudaFuncSetAttribute(gemm_qkv_kernel, cudaFuncAttributeMaxDynamicSharedMemorySize, QKV_SMEM);
    gemm_qkv_kernel<<<dim3(32, 12, BATCH), 256, QKV_SMEM>>>(wqf_p, xnf_p, b_qkv,
                                                            qf_p, kf_p, vf_p);

    // 3) attention (register-resident P), emits proj B-frags
    cudaFuncSetAttribute(attn_bf16_kernel, cudaFuncAttributeMaxDynamicSharedMemorySize, ATT_SMEM);
    attn_bf16_kernel<<<dim3(L / 128, BATCH * NH), 256, ATT_SMEM>>>(qf_p, kf_p, vf_p, attf_p);

    // 4) proj GEMM + bias + residual -> out
    gemm_bf16_kernel<<<dim3(32, 4, BATCH), 256>>>(wpf_p, attf_p, b_proj, x, out, C);
}